// round 2
// baseline (speedup 1.0000x reference)
#include <cuda_runtime.h>
#include <math.h>

// Problem constants (fixed by the dataset)
#define NN   10000   // nodes
#define NE   80000   // edges
#define NB   64      // graphs
#define NH   4       // heads
#define NC   256     // channels per head
#define DH   256     // node feature dim
#define HC   1024    // NH*NC
#define FEATD 896    // pooled feature dim

// ---------------- scratch (device globals; no allocation allowed) -----------
__device__ float g_x   [NN * DH];          // node features (updated per layer)
__device__ float g_h   [NE * 128];         // edge MLP hidden
__device__ float g_ea  [NE * DH];          // edge features
__device__ float g_q   [NN * HC];
__device__ float g_k   [NN * HC];
__device__ float g_v   [NN * HC];
__device__ float g_e   [NE * HC];          // per-edge projection (328 MB)
__device__ float g_alpha[NE * NH];         // logits, then exp()
__device__ float g_m   [NN * NH];          // segment max
__device__ float g_den [NN * NH];          // segment sum of exp
__device__ float g_agg [NN * HC];          // aggregated messages
__device__ float g_skip[NN * DH];          // skip projection
__device__ float g_feat[NB * FEATD];       // pooled features [mean|max|sum|en]
__device__ float g_cnt [NB];
__device__ float g_en1 [NB * 256];
__device__ float g_fc1 [NB * 1024];

// ---------------- generic tiled SGEMM: C = act(A[M,K] @ B[K,N] + bias) ------
// BM=BN=128, BK=8, 256 threads, 8x8 micro-tile per thread. Bounds-checked.
__global__ void sgemm_k(const float* __restrict__ A, const float* __restrict__ B,
                        const float* __restrict__ bias, float* __restrict__ C,
                        int M, int K, int Nn, int ldc, int act)
{
    __shared__ float As[8][128];
    __shared__ float Bs[8][128];
    const int tid = threadIdx.x;
    const int row0 = blockIdx.x * 128;
    const int col0 = blockIdx.y * 128;
    const int ty = tid >> 4;   // 0..15
    const int tx = tid & 15;   // 0..15

    float acc[8][8];
#pragma unroll
    for (int i = 0; i < 8; i++)
#pragma unroll
        for (int j = 0; j < 8; j++) acc[i][j] = 0.f;

    for (int k0 = 0; k0 < K; k0 += 8) {
#pragma unroll
        for (int i = 0; i < 4; i++) {            // A tile 128x8
            int idx = tid + i * 256;
            int r = idx >> 3, c = idx & 7;
            int gr = row0 + r, gc = k0 + c;
            As[c][r] = (gr < M && gc < K) ? A[(size_t)gr * K + gc] : 0.f;
        }
#pragma unroll
        for (int i = 0; i < 4; i++) {            // B tile 8x128
            int idx = tid + i * 256;
            int r = idx >> 7, c = idx & 127;
            int gr = k0 + r, gc = col0 + c;
            Bs[r][c] = (gr < K && gc < Nn) ? B[(size_t)gr * Nn + gc] : 0.f;
        }
        __syncthreads();
#pragma unroll
        for (int kk = 0; kk < 8; kk++) {
            float a[8], b[8];
#pragma unroll
            for (int i = 0; i < 8; i++) a[i] = As[kk][ty * 8 + i];
#pragma unroll
            for (int j = 0; j < 8; j++) b[j] = Bs[kk][tx * 8 + j];
#pragma unroll
            for (int i = 0; i < 8; i++)
#pragma unroll
                for (int j = 0; j < 8; j++) acc[i][j] += a[i] * b[j];
        }
        __syncthreads();
    }

#pragma unroll
    for (int i = 0; i < 8; i++) {
        int gr = row0 + ty * 8 + i;
        if (gr >= M) continue;
#pragma unroll
        for (int j = 0; j < 8; j++) {
            int gc = col0 + tx * 8 + j;
            if (gc >= Nn) continue;
            float v = acc[i][j];
            if (bias) v += bias[gc];
            if (act)  v = v > 0.f ? v : 0.01f * v;   // leaky relu 0.01
            C[(size_t)gr * ldc + gc] = v;
        }
    }
}

// ---------------- small helpers ---------------------------------------------
__global__ void fill_k(float* p, float v, int n)
{
    int i = blockIdx.x * blockDim.x + threadIdx.x;
    if (i < n) p[i] = v;
}

__global__ void embed_k(const int* __restrict__ ids, const float* __restrict__ emb,
                        float* __restrict__ x)
{
    int i = blockIdx.x * blockDim.x + threadIdx.x;
    if (i >= NN * DH) return;
    x[i] = emb[ids[i >> 8] * DH + (i & 255)];
}

// alpha[e,h] = (1/16) * sum_c q[tgt,h,c] * (k[src,h,c] + e[e,h,c])
__global__ void alpha_k(const int* __restrict__ src, const int* __restrict__ tgt,
                        const float* __restrict__ q, const float* __restrict__ k,
                        const float* __restrict__ e, float* __restrict__ alpha)
{
    int ed = blockIdx.x;
    int h = threadIdx.y, lane = threadIdx.x;
    int s = src[ed], t = tgt[ed];
    const float4* qp = (const float4*)(q + (size_t)t * HC + h * NC);
    const float4* kp = (const float4*)(k + (size_t)s * HC + h * NC);
    const float4* ep = (const float4*)(e + (size_t)ed * HC + h * NC);
    float acc = 0.f;
#pragma unroll
    for (int i = 0; i < 2; i++) {
        float4 qq = qp[lane + i * 32];
        float4 kk = kp[lane + i * 32];
        float4 ee = ep[lane + i * 32];
        acc += qq.x * (kk.x + ee.x) + qq.y * (kk.y + ee.y)
             + qq.z * (kk.z + ee.z) + qq.w * (kk.w + ee.w);
    }
#pragma unroll
    for (int o = 16; o; o >>= 1) acc += __shfl_xor_sync(0xffffffffu, acc, o);
    if (lane == 0) alpha[ed * NH + h] = acc * 0.0625f;
}

__device__ __forceinline__ void atomicMaxF(float* addr, float v)
{
    if (v >= 0.f) atomicMax((int*)addr, __float_as_int(v));
    else          atomicMin((unsigned int*)addr, __float_as_uint(v));
}

__global__ void seg_max_k(const int* __restrict__ tgt, const float* __restrict__ alpha,
                          float* __restrict__ m)
{
    int i = blockIdx.x * blockDim.x + threadIdx.x;
    if (i >= NE * NH) return;
    int ed = i >> 2, h = i & 3;
    atomicMaxF(&m[tgt[ed] * NH + h], alpha[i]);
}

__global__ void softmax_num_k(const int* __restrict__ tgt, float* __restrict__ alpha,
                              const float* __restrict__ m, float* __restrict__ den)
{
    int i = blockIdx.x * blockDim.x + threadIdx.x;
    if (i >= NE * NH) return;
    int ed = i >> 2, h = i & 3;
    int t = tgt[ed];
    float ex = expf(alpha[i] - m[t * NH + h]);
    alpha[i] = ex;
    atomicAdd(&den[t * NH + h], ex);
}

// agg[tgt,h,c] += (v[src,h,c] + e[e,h,c]) * a(e,h)
__global__ void msg_k(const int* __restrict__ src, const int* __restrict__ tgt,
                      const float* __restrict__ v, const float* __restrict__ e,
                      const float* __restrict__ ex, const float* __restrict__ den,
                      float* __restrict__ agg)
{
    int ed = blockIdx.x;
    int tpos = threadIdx.x;            // 256 threads, 4 consecutive floats each
    int s = src[ed], t = tgt[ed];
    int idx = tpos * 4;
    int h = idx >> 8;
    float a = ex[ed * NH + h] / (den[t * NH + h] + 1e-16f);
    float4 vv = *(const float4*)(v + (size_t)s * HC + idx);
    float4 ee = *(const float4*)(e + (size_t)ed * HC + idx);
    float* dst = agg + (size_t)t * HC + idx;
    atomicAdd(dst + 0, (vv.x + ee.x) * a);
    atomicAdd(dst + 1, (vv.y + ee.y) * a);
    atomicAdd(dst + 2, (vv.z + ee.z) * a);
    atomicAdd(dst + 3, (vv.w + ee.w) * a);
}

__global__ void combine_k(const float* __restrict__ agg, const float* __restrict__ skip,
                          float* __restrict__ x)
{
    int i = blockIdx.x * blockDim.x + threadIdx.x;
    if (i >= NN * DH) return;
    int n = i >> 8, c = i & 255;
    const float* ap = agg + (size_t)n * HC + c;
    x[i] = 0.25f * (ap[0] + ap[256] + ap[512] + ap[768]) + skip[i];
}

__global__ void cnt_k(const int* __restrict__ batch, float* __restrict__ cnt)
{
    int n = blockIdx.x * blockDim.x + threadIdx.x;
    if (n < NN) atomicAdd(&cnt[batch[n]], 1.f);
}

__global__ void pool_init_max_k(float* __restrict__ feat)
{
    int i = blockIdx.x * blockDim.x + threadIdx.x;
    if (i >= NB * 256) return;
    feat[(i >> 8) * FEATD + 256 + (i & 255)] = __int_as_float(0xff800000u); // -inf
}

__global__ void pool_k(const int* __restrict__ batch, const float* __restrict__ x,
                       float* __restrict__ feat)
{
    int i = blockIdx.x * blockDim.x + threadIdx.x;
    if (i >= NN * DH) return;
    int n = i >> 8, c = i & 255;
    int b = batch[n];
    float v = x[i];
    atomicAdd(&feat[b * FEATD + 512 + c], v);      // sum pool
    atomicMaxF(&feat[b * FEATD + 256 + c], v);     // max pool
}

__global__ void meanpool_k(float* __restrict__ feat, const float* __restrict__ cnt)
{
    int i = blockIdx.x * blockDim.x + threadIdx.x;
    if (i >= NB * 256) return;
    int b = i >> 8, c = i & 255;
    feat[b * FEATD + c] = feat[b * FEATD + 512 + c] / cnt[b];
}

// ---------------- launch -----------------------------------------------------
static inline dim3 gemm_grid(int M, int Nn)
{
    return dim3((M + 127) / 128, (Nn + 127) / 128);
}

extern "C" void kernel_launch(void* const* d_in, const int* in_sizes, int n_in,
                              void* d_out, int out_size)
{
    const int*   x_ids    = (const int*)  d_in[0];
    const int*   eidx     = (const int*)  d_in[1];
    const int*   batch    = (const int*)  d_in[2];
    const float* edge_attr= (const float*)d_in[3];
    const float* energies = (const float*)d_in[4];
    const float* node_emb = (const float*)d_in[5];
    const float* ew1      = (const float*)d_in[6];
    const float* eb1      = (const float*)d_in[7];
    const float* ew2      = (const float*)d_in[8];
    const float* eb2      = (const float*)d_in[9];
    const float* wq       = (const float*)d_in[10];
    const float* wk       = (const float*)d_in[11];
    const float* wv       = (const float*)d_in[12];
    const float* we       = (const float*)d_in[13];
    const float* wskip    = (const float*)d_in[14];
    const float* fce_w1   = (const float*)d_in[15];
    const float* fce_b1   = (const float*)d_in[16];
    const float* fce_w2   = (const float*)d_in[17];
    const float* fce_b2   = (const float*)d_in[18];
    const float* fc_w1    = (const float*)d_in[19];
    const float* fc_b1    = (const float*)d_in[20];
    const float* fc_w2    = (const float*)d_in[21];
    const float* fc_b2    = (const float*)d_in[22];
    float* out = (float*)d_out;

    const int* src = eidx;        // edge_index[0] = j (source)
    const int* tgt = eidx + NE;   // edge_index[1] = i (target)

    float *x, *h, *ea, *q, *k, *v, *e, *alpha, *m, *den, *agg, *skip, *feat, *cnt, *en1, *fc1;
    cudaGetSymbolAddress((void**)&x,    g_x);
    cudaGetSymbolAddress((void**)&h,    g_h);
    cudaGetSymbolAddress((void**)&ea,   g_ea);
    cudaGetSymbolAddress((void**)&q,    g_q);
    cudaGetSymbolAddress((void**)&k,    g_k);
    cudaGetSymbolAddress((void**)&v,    g_v);
    cudaGetSymbolAddress((void**)&e,    g_e);
    cudaGetSymbolAddress((void**)&alpha,g_alpha);
    cudaGetSymbolAddress((void**)&m,    g_m);
    cudaGetSymbolAddress((void**)&den,  g_den);
    cudaGetSymbolAddress((void**)&agg,  g_agg);
    cudaGetSymbolAddress((void**)&skip, g_skip);
    cudaGetSymbolAddress((void**)&feat, g_feat);
    cudaGetSymbolAddress((void**)&cnt,  g_cnt);
    cudaGetSymbolAddress((void**)&en1,  g_en1);
    cudaGetSymbolAddress((void**)&fc1,  g_fc1);

    const float NEG_INF = -INFINITY;   // host-legal

    // node embedding
    embed_k<<<(NN * DH + 255) / 256, 256>>>(x_ids, node_emb, x);

    // edge MLP: ea = lrelu(edge_attr @ ew1 + eb1) @ ew2 + eb2
    sgemm_k<<<gemm_grid(NE, 128), 256>>>(edge_attr, ew1, eb1, h,  NE, 14, 128, 128, 1);
    sgemm_k<<<gemm_grid(NE, 256), 256>>>(h,         ew2, eb2, ea, NE, 128, 256, 256, 0);

    for (int l = 0; l < 3; l++) {
        const float* wql = wq + (size_t)l * DH * HC;
        const float* wkl = wk + (size_t)l * DH * HC;
        const float* wvl = wv + (size_t)l * DH * HC;
        const float* wel = we + (size_t)l * DH * HC;
        const float* wsl = wskip + (size_t)l * DH * DH;

        sgemm_k<<<gemm_grid(NN, HC), 256>>>(x,  wql, nullptr, q,    NN, DH, HC, HC, 0);
        sgemm_k<<<gemm_grid(NN, HC), 256>>>(x,  wkl, nullptr, k,    NN, DH, HC, HC, 0);
        sgemm_k<<<gemm_grid(NN, HC), 256>>>(x,  wvl, nullptr, v,    NN, DH, HC, HC, 0);
        sgemm_k<<<gemm_grid(NE, HC), 256>>>(ea, wel, nullptr, e,    NE, DH, HC, HC, 0);
        sgemm_k<<<gemm_grid(NN, DH), 256>>>(x,  wsl, nullptr, skip, NN, DH, DH, DH, 0);

        alpha_k<<<NE, dim3(32, 4)>>>(src, tgt, q, k, e, alpha);

        fill_k<<<(NN * NH + 255) / 256, 256>>>(m,   NEG_INF, NN * NH);
        fill_k<<<(NN * NH + 255) / 256, 256>>>(den, 0.f,     NN * NH);
        seg_max_k    <<<(NE * NH + 255) / 256, 256>>>(tgt, alpha, m);
        softmax_num_k<<<(NE * NH + 255) / 256, 256>>>(tgt, alpha, m, den);

        fill_k<<<(NN * HC + 255) / 256, 256>>>(agg, 0.f, NN * HC);
        msg_k<<<NE, 256>>>(src, tgt, v, e, alpha, den, agg);

        combine_k<<<(NN * DH + 255) / 256, 256>>>(agg, skip, x);
    }

    // pooling
    fill_k<<<(NB * FEATD + 255) / 256, 256>>>(feat, 0.f, NB * FEATD);
    pool_init_max_k<<<(NB * 256 + 255) / 256, 256>>>(feat);
    fill_k<<<1, NB>>>(cnt, 0.f, NB);
    cnt_k<<<(NN + 255) / 256, 256>>>(batch, cnt);
    pool_k<<<(NN * DH + 255) / 256, 256>>>(batch, x, feat);
    meanpool_k<<<(NB * 256 + 255) / 256, 256>>>(feat, cnt);

    // energies MLP -> feat[:, 768:896]
    sgemm_k<<<gemm_grid(NB, 256), 256>>>(energies, fce_w1, fce_b1, en1, NB, 201, 256, 256, 1);
    sgemm_k<<<gemm_grid(NB, 128), 256>>>(en1, fce_w2, fce_b2, feat + 768, NB, 256, 128, FEATD, 0);

    // final MLP
    sgemm_k<<<gemm_grid(NB, 1024), 256>>>(feat, fc_w1, fc_b1, fc1, NB, FEATD, 1024, 1024, 1);
    sgemm_k<<<gemm_grid(NB, 804),  256>>>(fc1,  fc_w2, fc_b2, out, NB, 1024,  804,  804,  0);
}

// round 3
// speedup vs baseline: 1.5984x; 1.5984x over previous
#include <cuda_runtime.h>
#include <math.h>

#define NN   10000
#define NE   80000
#define NB   64
#define NH   4
#define NC   256
#define DH   256
#define HC   1024
#define FEATD 896

// ---------------- scratch ----------------------------------------------------
__device__ float g_x    [NN * DH];
__device__ float g_h    [NE * 128];
__device__ float g_ea   [NE * DH];
__device__ float g_wcat [DH * 2048];     // [Wqk_0..3 | Wqe_0..3]
__device__ float g_wst  [HC * DH];       // we_stack[h*256+d, c]
__device__ float g_ucat [NN * 2048];     // [u | qw]
__device__ float g_v    [NN * HC];
__device__ float g_skip [NN * DH];
__device__ float g_alpha[NE * NH];
__device__ float g_m    [NN * NH];
__device__ float g_den  [NN * NH];
__device__ float g_aggV [NN * HC];
__device__ float g_wea  [NN * HC];
__device__ float g_aggE [NN * DH];
__device__ float g_feat [NB * FEATD];
__device__ float g_cnt  [NB];
__device__ float g_en1  [NB * 256];
__device__ float g_fc1  [NB * 1024];

// ---------------- gemm2: fast path, requires K%16==0, N%4==0 ----------------
// C[M,N] = act(A[M,K] @ B + bias); flags bit0 = leakyrelu, bit1 = B transposed
// (B[j*ldb+k] instead of B[k*ldb+j]). 128x128 tile, BK=16, double-buffered.
__global__ __launch_bounds__(256) void gemm2(
    const float* __restrict__ A, const float* __restrict__ B,
    const float* __restrict__ bias, float* __restrict__ C,
    int M, int K, int N, int lda, int ldb, int ldc, int flags)
{
    __shared__ float As[2][16][128];
    __shared__ float Bs[2][16][128];
    const int tid  = threadIdx.x;
    const int row0 = blockIdx.x * 128;
    const int col0 = blockIdx.y * 128;
    const int ty   = tid >> 4;
    const int tx   = tid & 15;
    const bool bt  = (flags & 2) != 0;
    const int nT   = K / 16;

    float4 aReg[2], bReg[2];
    float acc[8][8];
#pragma unroll
    for (int i = 0; i < 8; i++)
#pragma unroll
        for (int j = 0; j < 8; j++) acc[i][j] = 0.f;

    auto fetch = [&](int kt) {
        int k0 = kt * 16;
#pragma unroll
        for (int i = 0; i < 2; i++) {
            int idx = tid + 256 * i;
            int m = idx >> 2, kq = idx & 3;
            int gr = row0 + m;
            aReg[i] = (gr < M) ? *(const float4*)(A + (size_t)gr * lda + k0 + kq * 4)
                               : make_float4(0.f, 0.f, 0.f, 0.f);
        }
        if (!bt) {
#pragma unroll
            for (int i = 0; i < 2; i++) {
                int idx = tid + 256 * i;
                int kk2 = idx >> 5, j = (idx & 31) * 4;
                int gc = col0 + j;
                bReg[i] = (gc < N) ? *(const float4*)(B + (size_t)(k0 + kk2) * ldb + gc)
                                   : make_float4(0.f, 0.f, 0.f, 0.f);
            }
        } else {
#pragma unroll
            for (int i = 0; i < 2; i++) {
                int idx = tid + 256 * i;
                int j = idx >> 2, kq = idx & 3;
                int gc = col0 + j;
                bReg[i] = (gc < N) ? *(const float4*)(B + (size_t)gc * ldb + k0 + kq * 4)
                                   : make_float4(0.f, 0.f, 0.f, 0.f);
            }
        }
    };
    auto store = [&](int buf) {
#pragma unroll
        for (int i = 0; i < 2; i++) {
            int idx = tid + 256 * i;
            int m = idx >> 2, kq = idx & 3;
            As[buf][kq * 4 + 0][m] = aReg[i].x;
            As[buf][kq * 4 + 1][m] = aReg[i].y;
            As[buf][kq * 4 + 2][m] = aReg[i].z;
            As[buf][kq * 4 + 3][m] = aReg[i].w;
        }
        if (!bt) {
#pragma unroll
            for (int i = 0; i < 2; i++) {
                int idx = tid + 256 * i;
                int kk2 = idx >> 5, j = (idx & 31) * 4;
                *(float4*)&Bs[buf][kk2][j] = bReg[i];
            }
        } else {
#pragma unroll
            for (int i = 0; i < 2; i++) {
                int idx = tid + 256 * i;
                int j = idx >> 2, kq = idx & 3;
                Bs[buf][kq * 4 + 0][j] = bReg[i].x;
                Bs[buf][kq * 4 + 1][j] = bReg[i].y;
                Bs[buf][kq * 4 + 2][j] = bReg[i].z;
                Bs[buf][kq * 4 + 3][j] = bReg[i].w;
            }
        }
    };

    fetch(0); store(0);
    if (nT > 1) fetch(1);
    __syncthreads();

    for (int t = 0; t < nT; t++) {
        int cur = t & 1;
#pragma unroll
        for (int kk = 0; kk < 16; kk++) {
            float4 a0 = *(const float4*)&As[cur][kk][ty * 8];
            float4 a1 = *(const float4*)&As[cur][kk][ty * 8 + 4];
            float4 b0 = *(const float4*)&Bs[cur][kk][tx * 8];
            float4 b1 = *(const float4*)&Bs[cur][kk][tx * 8 + 4];
            float av[8] = {a0.x, a0.y, a0.z, a0.w, a1.x, a1.y, a1.z, a1.w};
            float bv[8] = {b0.x, b0.y, b0.z, b0.w, b1.x, b1.y, b1.z, b1.w};
#pragma unroll
            for (int i = 0; i < 8; i++)
#pragma unroll
                for (int j = 0; j < 8; j++) acc[i][j] += av[i] * bv[j];
        }
        if (t + 1 < nT) store((t + 1) & 1);
        if (t + 2 < nT) fetch(t + 2);
        __syncthreads();
    }

#pragma unroll
    for (int i = 0; i < 8; i++) {
        int gr = row0 + ty * 8 + i;
        if (gr >= M) continue;
#pragma unroll
        for (int j = 0; j < 8; j++) {
            int gc = col0 + tx * 8 + j;
            if (gc >= N) continue;
            float vv = acc[i][j];
            if (bias) vv += bias[gc];
            if (flags & 1) vv = vv > 0.f ? vv : 0.01f * vv;
            C[(size_t)gr * ldc + gc] = vv;
        }
    }
}

// ---------------- legacy sgemm (for ragged K / tiny M cases) -----------------
__global__ void sgemm_k(const float* __restrict__ A, const float* __restrict__ B,
                        const float* __restrict__ bias, float* __restrict__ C,
                        int M, int K, int Nn, int ldc, int act)
{
    __shared__ float As[8][128];
    __shared__ float Bs[8][128];
    const int tid = threadIdx.x;
    const int row0 = blockIdx.x * 128;
    const int col0 = blockIdx.y * 128;
    const int ty = tid >> 4;
    const int tx = tid & 15;

    float acc[8][8];
#pragma unroll
    for (int i = 0; i < 8; i++)
#pragma unroll
        for (int j = 0; j < 8; j++) acc[i][j] = 0.f;

    for (int k0 = 0; k0 < K; k0 += 8) {
#pragma unroll
        for (int i = 0; i < 4; i++) {
            int idx = tid + i * 256;
            int r = idx >> 3, c = idx & 7;
            int gr = row0 + r, gc = k0 + c;
            As[c][r] = (gr < M && gc < K) ? A[(size_t)gr * K + gc] : 0.f;
        }
#pragma unroll
        for (int i = 0; i < 4; i++) {
            int idx = tid + i * 256;
            int r = idx >> 7, c = idx & 127;
            int gr = k0 + r, gc = col0 + c;
            Bs[r][c] = (gr < K && gc < Nn) ? B[(size_t)gr * Nn + gc] : 0.f;
        }
        __syncthreads();
#pragma unroll
        for (int kk = 0; kk < 8; kk++) {
            float a[8], b[8];
#pragma unroll
            for (int i = 0; i < 8; i++) a[i] = As[kk][ty * 8 + i];
#pragma unroll
            for (int j = 0; j < 8; j++) b[j] = Bs[kk][tx * 8 + j];
#pragma unroll
            for (int i = 0; i < 8; i++)
#pragma unroll
                for (int j = 0; j < 8; j++) acc[i][j] += a[i] * b[j];
        }
        __syncthreads();
    }

#pragma unroll
    for (int i = 0; i < 8; i++) {
        int gr = row0 + ty * 8 + i;
        if (gr >= M) continue;
#pragma unroll
        for (int j = 0; j < 8; j++) {
            int gc = col0 + tx * 8 + j;
            if (gc >= Nn) continue;
            float v = acc[i][j];
            if (bias) v += bias[gc];
            if (act)  v = v > 0.f ? v : 0.01f * v;
            C[(size_t)gr * ldc + gc] = v;
        }
    }
}

// ---------------- weight prep: Wqk_h = Wq_h@Wk_h^T, Wqe_h = Wq_h@We_h^T ------
// grid (4,4,8): z = h*2 + which(0=qk,1=qe). 64x64 tiles, 256 threads, 4x4 micro.
__global__ __launch_bounds__(256) void wprep_k(const float* __restrict__ wq_l,
                                               const float* __restrict__ wk_l,
                                               const float* __restrict__ we_l,
                                               float* __restrict__ wcat)
{
    int z = blockIdx.z;
    int h = z >> 1, which = z & 1;
    const float* A = wq_l + h * 256;                       // A[i,c], lda 1024
    const float* B = (which ? we_l : wk_l) + h * 256;      // B[j,c], ldb 1024
    float* C = wcat + (which ? 1024 : 0) + h * 256;        // ldc 2048

    __shared__ float As[16][64];
    __shared__ float Bs[16][64];
    int tid = threadIdx.x;
    int ty = tid >> 4, tx = tid & 15;
    float acc[4][4];
#pragma unroll
    for (int i = 0; i < 4; i++)
#pragma unroll
        for (int j = 0; j < 4; j++) acc[i][j] = 0.f;

    for (int k0 = 0; k0 < 256; k0 += 16) {
        int m = tid >> 2, kq = tid & 3;
        float4 a4 = *(const float4*)(A + (size_t)(blockIdx.x * 64 + m) * 1024 + k0 + kq * 4);
        As[kq * 4 + 0][m] = a4.x; As[kq * 4 + 1][m] = a4.y;
        As[kq * 4 + 2][m] = a4.z; As[kq * 4 + 3][m] = a4.w;
        float4 b4 = *(const float4*)(B + (size_t)(blockIdx.y * 64 + m) * 1024 + k0 + kq * 4);
        Bs[kq * 4 + 0][m] = b4.x; Bs[kq * 4 + 1][m] = b4.y;
        Bs[kq * 4 + 2][m] = b4.z; Bs[kq * 4 + 3][m] = b4.w;
        __syncthreads();
#pragma unroll
        for (int kk = 0; kk < 16; kk++) {
            float a[4], b[4];
#pragma unroll
            for (int i = 0; i < 4; i++) a[i] = As[kk][ty * 4 + i];
#pragma unroll
            for (int j = 0; j < 4; j++) b[j] = Bs[kk][tx * 4 + j];
#pragma unroll
            for (int i = 0; i < 4; i++)
#pragma unroll
                for (int j = 0; j < 4; j++) acc[i][j] += a[i] * b[j];
        }
        __syncthreads();
    }
#pragma unroll
    for (int i = 0; i < 4; i++)
#pragma unroll
        for (int j = 0; j < 4; j++)
            C[(size_t)(blockIdx.x * 64 + ty * 4 + i) * 2048 + blockIdx.y * 64 + tx * 4 + j] = acc[i][j];
}

// westack[h*256+d, c] = we_l[d, h*256+c]
__global__ void pack_we_k(const float* __restrict__ we_l, float* __restrict__ wst)
{
    int i = blockIdx.x * blockDim.x + threadIdx.x;
    if (i >= HC * DH) return;
    int r = i >> 8, c = i & 255;
    int h = r >> 8, d = r & 255;
    wst[i] = we_l[d * 1024 + h * 256 + c];
}

// ---------------- helpers ----------------------------------------------------
__global__ void fill_k(float* p, float v, int n)
{
    int i = blockIdx.x * blockDim.x + threadIdx.x;
    if (i < n) p[i] = v;
}

__global__ void embed_k(const int* __restrict__ ids, const float* __restrict__ emb,
                        float* __restrict__ x)
{
    int i = blockIdx.x * blockDim.x + threadIdx.x;
    if (i >= NN * DH) return;
    x[i] = emb[ids[i >> 8] * DH + (i & 255)];
}

// alpha[e,h] = (1/16) * ( u[t,h]·x[s] + qw[t,h]·ea[e] )
__global__ void alpha2_k(const int* __restrict__ src, const int* __restrict__ tgt,
                         const float* __restrict__ ucat, const float* __restrict__ x,
                         const float* __restrict__ ea, float* __restrict__ alpha)
{
    int e = blockIdx.x;
    int h = threadIdx.y, lane = threadIdx.x;
    int s = src[e], t = tgt[e];
    const float4* up  = (const float4*)(ucat + (size_t)t * 2048 + h * 256);
    const float4* qwp = (const float4*)(ucat + (size_t)t * 2048 + 1024 + h * 256);
    const float4* xp  = (const float4*)(x + (size_t)s * 256);
    const float4* eap = (const float4*)(ea + (size_t)e * 256);
    float acc = 0.f;
#pragma unroll
    for (int i = 0; i < 2; i++) {
        float4 u4 = up[lane + i * 32],  x4 = xp[lane + i * 32];
        float4 q4 = qwp[lane + i * 32], e4 = eap[lane + i * 32];
        acc += u4.x * x4.x + u4.y * x4.y + u4.z * x4.z + u4.w * x4.w;
        acc += q4.x * e4.x + q4.y * e4.y + q4.z * e4.z + q4.w * e4.w;
    }
#pragma unroll
    for (int o = 16; o; o >>= 1) acc += __shfl_xor_sync(0xffffffffu, acc, o);
    if (lane == 0) alpha[e * NH + h] = acc * 0.0625f;
}

__device__ __forceinline__ void atomicMaxF(float* addr, float v)
{
    if (v >= 0.f) atomicMax((int*)addr, __float_as_int(v));
    else          atomicMin((unsigned int*)addr, __float_as_uint(v));
}

__global__ void seg_max_k(const int* __restrict__ tgt, const float* __restrict__ alpha,
                          float* __restrict__ m)
{
    int i = blockIdx.x * blockDim.x + threadIdx.x;
    if (i >= NE * NH) return;
    int ed = i >> 2, h = i & 3;
    atomicMaxF(&m[tgt[ed] * NH + h], alpha[i]);
}

__global__ void softmax_num_k(const int* __restrict__ tgt, float* __restrict__ alpha,
                              const float* __restrict__ m, float* __restrict__ den)
{
    int i = blockIdx.x * blockDim.x + threadIdx.x;
    if (i >= NE * NH) return;
    int ed = i >> 2, h = i & 3;
    int t = tgt[ed];
    float ex = expf(alpha[i] - m[t * NH + h]);
    alpha[i] = ex;
    atomicAdd(&den[t * NH + h], ex);
}

// aggV[t,h,c] += a*v[s,h,c];  wea[t,h,d] += a*ea[e,d]
__global__ void scatter_k(const int* __restrict__ src, const int* __restrict__ tgt,
                          const float* __restrict__ v, const float* __restrict__ ea,
                          const float* __restrict__ ex, const float* __restrict__ den,
                          float* __restrict__ aggV, float* __restrict__ wea)
{
    int e = blockIdx.x;
    int tid = threadIdx.x;
    int s = src[e], t = tgt[e];
    int idx = tid * 4;
    int h = idx >> 8;
    float a = ex[e * NH + h] / (den[t * NH + h] + 1e-16f);
    float4 v4 = *(const float4*)(v + (size_t)s * HC + idx);
    float4 e4 = *(const float4*)(ea + (size_t)e * 256 + (idx & 255));
    float* d1 = aggV + (size_t)t * HC + idx;
    atomicAdd(d1 + 0, v4.x * a);
    atomicAdd(d1 + 1, v4.y * a);
    atomicAdd(d1 + 2, v4.z * a);
    atomicAdd(d1 + 3, v4.w * a);
    float* d2 = wea + (size_t)t * HC + idx;
    atomicAdd(d2 + 0, e4.x * a);
    atomicAdd(d2 + 1, e4.y * a);
    atomicAdd(d2 + 2, e4.z * a);
    atomicAdd(d2 + 3, e4.w * a);
}

__global__ void combine2_k(const float* __restrict__ aggV, const float* __restrict__ aggE,
                           const float* __restrict__ skip, float* __restrict__ x)
{
    int i = blockIdx.x * blockDim.x + threadIdx.x;
    if (i >= NN * DH) return;
    int n = i >> 8, c = i & 255;
    const float* ap = aggV + (size_t)n * HC + c;
    float s4 = ap[0] + ap[256] + ap[512] + ap[768];
    x[i] = 0.25f * (s4 + aggE[n * DH + c]) + skip[i];
}

__global__ void cnt_k(const int* __restrict__ batch, float* __restrict__ cnt)
{
    int n = blockIdx.x * blockDim.x + threadIdx.x;
    if (n < NN) atomicAdd(&cnt[batch[n]], 1.f);
}

__global__ void pool_init_max_k(float* __restrict__ feat)
{
    int i = blockIdx.x * blockDim.x + threadIdx.x;
    if (i >= NB * 256) return;
    feat[(i >> 8) * FEATD + 256 + (i & 255)] = __int_as_float(0xff800000u);
}

__global__ void pool_k(const int* __restrict__ batch, const float* __restrict__ x,
                       float* __restrict__ feat)
{
    int i = blockIdx.x * blockDim.x + threadIdx.x;
    if (i >= NN * DH) return;
    int n = i >> 8, c = i & 255;
    int b = batch[n];
    float v = x[i];
    atomicAdd(&feat[b * FEATD + 512 + c], v);
    atomicMaxF(&feat[b * FEATD + 256 + c], v);
}

__global__ void meanpool_k(float* __restrict__ feat, const float* __restrict__ cnt)
{
    int i = blockIdx.x * blockDim.x + threadIdx.x;
    if (i >= NB * 256) return;
    int b = i >> 8, c = i & 255;
    feat[b * FEATD + c] = feat[b * FEATD + 512 + c] / cnt[b];
}

// ---------------- launch -----------------------------------------------------
static inline dim3 g128(int M, int Nn) { return dim3((M + 127) / 128, (Nn + 127) / 128); }

extern "C" void kernel_launch(void* const* d_in, const int* in_sizes, int n_in,
                              void* d_out, int out_size)
{
    const int*   x_ids    = (const int*)  d_in[0];
    const int*   eidx     = (const int*)  d_in[1];
    const int*   batch    = (const int*)  d_in[2];
    const float* edge_attr= (const float*)d_in[3];
    const float* energies = (const float*)d_in[4];
    const float* node_emb = (const float*)d_in[5];
    const float* ew1      = (const float*)d_in[6];
    const float* eb1      = (const float*)d_in[7];
    const float* ew2      = (const float*)d_in[8];
    const float* eb2      = (const float*)d_in[9];
    const float* wq       = (const float*)d_in[10];
    const float* wk       = (const float*)d_in[11];
    const float* wv       = (const float*)d_in[12];
    const float* we       = (const float*)d_in[13];
    const float* wskip    = (const float*)d_in[14];
    const float* fce_w1   = (const float*)d_in[15];
    const float* fce_b1   = (const float*)d_in[16];
    const float* fce_w2   = (const float*)d_in[17];
    const float* fce_b2   = (const float*)d_in[18];
    const float* fc_w1    = (const float*)d_in[19];
    const float* fc_b1    = (const float*)d_in[20];
    const float* fc_w2    = (const float*)d_in[21];
    const float* fc_b2    = (const float*)d_in[22];
    float* out = (float*)d_out;

    const int* src = eidx;
    const int* tgt = eidx + NE;

    float *x, *h, *ea, *wcat, *wst, *ucat, *v, *skip, *alpha, *m, *den,
          *aggV, *wea, *aggE, *feat, *cnt, *en1, *fc1;
    cudaGetSymbolAddress((void**)&x,    g_x);
    cudaGetSymbolAddress((void**)&h,    g_h);
    cudaGetSymbolAddress((void**)&ea,   g_ea);
    cudaGetSymbolAddress((void**)&wcat, g_wcat);
    cudaGetSymbolAddress((void**)&wst,  g_wst);
    cudaGetSymbolAddress((void**)&ucat, g_ucat);
    cudaGetSymbolAddress((void**)&v,    g_v);
    cudaGetSymbolAddress((void**)&skip, g_skip);
    cudaGetSymbolAddress((void**)&alpha,g_alpha);
    cudaGetSymbolAddress((void**)&m,    g_m);
    cudaGetSymbolAddress((void**)&den,  g_den);
    cudaGetSymbolAddress((void**)&aggV, g_aggV);
    cudaGetSymbolAddress((void**)&wea,  g_wea);
    cudaGetSymbolAddress((void**)&aggE, g_aggE);
    cudaGetSymbolAddress((void**)&feat, g_feat);
    cudaGetSymbolAddress((void**)&cnt,  g_cnt);
    cudaGetSymbolAddress((void**)&en1,  g_en1);
    cudaGetSymbolAddress((void**)&fc1,  g_fc1);

    const float NEG_INF = -INFINITY;

    // node embedding
    embed_k<<<(NN * DH + 255) / 256, 256>>>(x_ids, node_emb, x);

    // edge MLP
    sgemm_k<<<g128(NE, 128), 256>>>(edge_attr, ew1, eb1, h, NE, 14, 128, 128, 1);
    gemm2<<<g128(NE, 256), 256>>>(h, ew2, eb2, ea, NE, 128, 256, 128, 256, 256, 0);

    for (int l = 0; l < 3; l++) {
        const float* wql = wq + (size_t)l * DH * HC;
        const float* wkl = wk + (size_t)l * DH * HC;
        const float* wvl = wv + (size_t)l * DH * HC;
        const float* wel = we + (size_t)l * DH * HC;
        const float* wsl = wskip + (size_t)l * DH * DH;

        // weight-level precompute
        wprep_k<<<dim3(4, 4, 8), 256>>>(wql, wkl, wel, wcat);
        pack_we_k<<<(HC * DH + 255) / 256, 256>>>(wel, wst);

        // node GEMMs
        gemm2<<<g128(NN, 2048), 256>>>(x, wcat, nullptr, ucat, NN, 256, 2048, 256, 2048, 2048, 0);
        gemm2<<<g128(NN, HC),   256>>>(x, wvl,  nullptr, v,    NN, 256, 1024, 256, 1024, 1024, 0);
        gemm2<<<g128(NN, DH),   256>>>(x, wsl,  nullptr, skip, NN, 256, 256,  256, 256,  256,  0);

        // attention logits + segment softmax
        alpha2_k<<<NE, dim3(32, 4)>>>(src, tgt, ucat, x, ea, alpha);
        fill_k<<<(NN * NH + 255) / 256, 256>>>(m,   NEG_INF, NN * NH);
        fill_k<<<(NN * NH + 255) / 256, 256>>>(den, 0.f,     NN * NH);
        seg_max_k    <<<(NE * NH + 255) / 256, 256>>>(tgt, alpha, m);
        softmax_num_k<<<(NE * NH + 255) / 256, 256>>>(tgt, alpha, m, den);

        // weighted scatter of v and ea
        fill_k<<<(NN * HC + 255) / 256, 256>>>(aggV, 0.f, NN * HC);
        fill_k<<<(NN * HC + 255) / 256, 256>>>(wea,  0.f, NN * HC);
        scatter_k<<<NE, 256>>>(src, tgt, v, ea, alpha, den, aggV, wea);

        // edge contribution via node GEMM, then combine
        gemm2<<<g128(NN, DH), 256>>>(wea, wst, nullptr, aggE, NN, 1024, 256, 1024, 256, 256, 0);
        combine2_k<<<(NN * DH + 255) / 256, 256>>>(aggV, aggE, skip, x);
    }

    // pooling
    fill_k<<<(NB * FEATD + 255) / 256, 256>>>(feat, 0.f, NB * FEATD);
    pool_init_max_k<<<(NB * 256 + 255) / 256, 256>>>(feat);
    fill_k<<<1, NB>>>(cnt, 0.f, NB);
    cnt_k<<<(NN + 255) / 256, 256>>>(batch, cnt);
    pool_k<<<(NN * DH + 255) / 256, 256>>>(batch, x, feat);
    meanpool_k<<<(NB * 256 + 255) / 256, 256>>>(feat, cnt);

    // energies MLP
    sgemm_k<<<g128(NB, 256), 256>>>(energies, fce_w1, fce_b1, en1, NB, 201, 256, 256, 1);
    sgemm_k<<<g128(NB, 128), 256>>>(en1, fce_w2, fce_b2, feat + 768, NB, 256, 128, FEATD, 0);

    // final MLP
    sgemm_k<<<g128(NB, 1024), 256>>>(feat, fc_w1, fc_b1, fc1, NB, FEATD, 1024, 1024, 1);
    sgemm_k<<<g128(NB, 804),  256>>>(fc1,  fc_w2, fc_b2, out, NB, 1024,  804,  804,  0);
}

// round 4
// speedup vs baseline: 2.1122x; 1.3215x over previous
#include <cuda_runtime.h>
#include <math.h>

#define NN   10000
#define NE   80000
#define NB   64
#define NH   4
#define DH   256
#define HC   1024
#define FEATD 896

// uall column layout: [u(1024) | qw(1024) | v(1024) | skip(256)]
#define WALLN 3328
#define OFF_U    0
#define OFF_QW   1024
#define OFF_V    2048
#define OFF_SKIP 3072

// ---------------- scratch ----------------------------------------------------
__device__ float g_x    [NN * DH];
__device__ float g_h    [NE * 128];
__device__ float g_ea   [NE * DH];
__device__ float g_wall [DH * WALLN];
__device__ float g_wst  [HC * DH];
__device__ float g_uall [NN * WALLN];
__device__ float g_alpha[NE * NH];
__device__ float g_aggVs[NN * DH];
__device__ float g_wea  [NN * HC];
__device__ float g_aggE [NN * DH];
__device__ float g_feat [NB * FEATD];
__device__ float g_cnt  [NB];
__device__ float g_en1  [NB * 256];
__device__ float g_fc1  [NB * 1024];
__device__ int   g_deg  [NN];
__device__ int   g_off  [NN + 1];
__device__ int   g_cur  [NN];
__device__ int   g_perm [NE];

// ---------------- gemm2: K%16==0, 128x128 tile, BK=16, double-buffered -------
__global__ __launch_bounds__(256) void gemm2(
    const float* __restrict__ A, const float* __restrict__ B,
    const float* __restrict__ bias, float* __restrict__ C,
    int M, int K, int N, int lda, int ldb, int ldc, int flags)
{
    __shared__ float As[2][16][128];
    __shared__ float Bs[2][16][128];
    const int tid  = threadIdx.x;
    const int row0 = blockIdx.x * 128;
    const int col0 = blockIdx.y * 128;
    const int ty   = tid >> 4;
    const int tx   = tid & 15;
    const int nT   = K / 16;

    float4 aReg[2], bReg[2];
    float acc[8][8];
#pragma unroll
    for (int i = 0; i < 8; i++)
#pragma unroll
        for (int j = 0; j < 8; j++) acc[i][j] = 0.f;

    auto fetch = [&](int kt) {
        int k0 = kt * 16;
#pragma unroll
        for (int i = 0; i < 2; i++) {
            int idx = tid + 256 * i;
            int m = idx >> 2, kq = idx & 3;
            int gr = row0 + m;
            aReg[i] = (gr < M) ? *(const float4*)(A + (size_t)gr * lda + k0 + kq * 4)
                               : make_float4(0.f, 0.f, 0.f, 0.f);
        }
#pragma unroll
        for (int i = 0; i < 2; i++) {
            int idx = tid + 256 * i;
            int kk2 = idx >> 5, j = (idx & 31) * 4;
            int gc = col0 + j;
            bReg[i] = (gc < N) ? *(const float4*)(B + (size_t)(k0 + kk2) * ldb + gc)
                               : make_float4(0.f, 0.f, 0.f, 0.f);
        }
    };
    auto store = [&](int buf) {
#pragma unroll
        for (int i = 0; i < 2; i++) {
            int idx = tid + 256 * i;
            int m = idx >> 2, kq = idx & 3;
            As[buf][kq * 4 + 0][m] = aReg[i].x;
            As[buf][kq * 4 + 1][m] = aReg[i].y;
            As[buf][kq * 4 + 2][m] = aReg[i].z;
            As[buf][kq * 4 + 3][m] = aReg[i].w;
        }
#pragma unroll
        for (int i = 0; i < 2; i++) {
            int idx = tid + 256 * i;
            int kk2 = idx >> 5, j = (idx & 31) * 4;
            *(float4*)&Bs[buf][kk2][j] = bReg[i];
        }
    };

    fetch(0); store(0);
    if (nT > 1) fetch(1);
    __syncthreads();

    for (int t = 0; t < nT; t++) {
        int cur = t & 1;
#pragma unroll
        for (int kk = 0; kk < 16; kk++) {
            float4 a0 = *(const float4*)&As[cur][kk][ty * 8];
            float4 a1 = *(const float4*)&As[cur][kk][ty * 8 + 4];
            float4 b0 = *(const float4*)&Bs[cur][kk][tx * 8];
            float4 b1 = *(const float4*)&Bs[cur][kk][tx * 8 + 4];
            float av[8] = {a0.x, a0.y, a0.z, a0.w, a1.x, a1.y, a1.z, a1.w};
            float bv[8] = {b0.x, b0.y, b0.z, b0.w, b1.x, b1.y, b1.z, b1.w};
#pragma unroll
            for (int i = 0; i < 8; i++)
#pragma unroll
                for (int j = 0; j < 8; j++) acc[i][j] += av[i] * bv[j];
        }
        if (t + 1 < nT) store((t + 1) & 1);
        if (t + 2 < nT) fetch(t + 2);
        __syncthreads();
    }

#pragma unroll
    for (int i = 0; i < 8; i++) {
        int gr = row0 + ty * 8 + i;
        if (gr >= M) continue;
#pragma unroll
        for (int j = 0; j < 8; j++) {
            int gc = col0 + tx * 8 + j;
            if (gc >= N) continue;
            float vv = acc[i][j];
            if (bias) vv += bias[gc];
            if (flags & 1) vv = vv > 0.f ? vv : 0.01f * vv;
            C[(size_t)gr * ldc + gc] = vv;
        }
    }
}

// ---------------- legacy sgemm (ragged K / tiny M) ---------------------------
__global__ void sgemm_k(const float* __restrict__ A, const float* __restrict__ B,
                        const float* __restrict__ bias, float* __restrict__ C,
                        int M, int K, int Nn, int ldc, int act)
{
    __shared__ float As[8][128];
    __shared__ float Bs[8][128];
    const int tid = threadIdx.x;
    const int row0 = blockIdx.x * 128;
    const int col0 = blockIdx.y * 128;
    const int ty = tid >> 4;
    const int tx = tid & 15;

    float acc[8][8];
#pragma unroll
    for (int i = 0; i < 8; i++)
#pragma unroll
        for (int j = 0; j < 8; j++) acc[i][j] = 0.f;

    for (int k0 = 0; k0 < K; k0 += 8) {
#pragma unroll
        for (int i = 0; i < 4; i++) {
            int idx = tid + i * 256;
            int r = idx >> 3, c = idx & 7;
            int gr = row0 + r, gc = k0 + c;
            As[c][r] = (gr < M && gc < K) ? A[(size_t)gr * K + gc] : 0.f;
        }
#pragma unroll
        for (int i = 0; i < 4; i++) {
            int idx = tid + i * 256;
            int r = idx >> 7, c = idx & 127;
            int gr = k0 + r, gc = col0 + c;
            Bs[r][c] = (gr < K && gc < Nn) ? B[(size_t)gr * Nn + gc] : 0.f;
        }
        __syncthreads();
#pragma unroll
        for (int kk = 0; kk < 8; kk++) {
            float a[8], b[8];
#pragma unroll
            for (int i = 0; i < 8; i++) a[i] = As[kk][ty * 8 + i];
#pragma unroll
            for (int j = 0; j < 8; j++) b[j] = Bs[kk][tx * 8 + j];
#pragma unroll
            for (int i = 0; i < 8; i++)
#pragma unroll
                for (int j = 0; j < 8; j++) acc[i][j] += a[i] * b[j];
        }
        __syncthreads();
    }

#pragma unroll
    for (int i = 0; i < 8; i++) {
        int gr = row0 + ty * 8 + i;
        if (gr >= M) continue;
#pragma unroll
        for (int j = 0; j < 8; j++) {
            int gc = col0 + tx * 8 + j;
            if (gc >= Nn) continue;
            float v = acc[i][j];
            if (bias) v += bias[gc];
            if (act)  v = v > 0.f ? v : 0.01f * v;
            C[(size_t)gr * ldc + gc] = v;
        }
    }
}

// ---------------- weight prep: Wqk_h=Wq_h@Wk_h^T, Wqe_h=Wq_h@We_h^T into wall
__global__ __launch_bounds__(256) void wprep_k(const float* __restrict__ wq_l,
                                               const float* __restrict__ wk_l,
                                               const float* __restrict__ we_l,
                                               float* __restrict__ wall)
{
    int z = blockIdx.z;
    int h = z >> 1, which = z & 1;
    const float* A = wq_l + h * 256;                    // [i,c], lda 1024
    const float* B = (which ? we_l : wk_l) + h * 256;   // [j,c], ldb 1024
    float* C = wall + (which ? OFF_QW : OFF_U) + h * 256;

    __shared__ float As[16][64];
    __shared__ float Bs[16][64];
    int tid = threadIdx.x;
    int ty = tid >> 4, tx = tid & 15;
    float acc[4][4];
#pragma unroll
    for (int i = 0; i < 4; i++)
#pragma unroll
        for (int j = 0; j < 4; j++) acc[i][j] = 0.f;

    for (int k0 = 0; k0 < 256; k0 += 16) {
        int m = tid >> 2, kq = tid & 3;
        float4 a4 = *(const float4*)(A + (size_t)(blockIdx.x * 64 + m) * 1024 + k0 + kq * 4);
        As[kq * 4 + 0][m] = a4.x; As[kq * 4 + 1][m] = a4.y;
        As[kq * 4 + 2][m] = a4.z; As[kq * 4 + 3][m] = a4.w;
        float4 b4 = *(const float4*)(B + (size_t)(blockIdx.y * 64 + m) * 1024 + k0 + kq * 4);
        Bs[kq * 4 + 0][m] = b4.x; Bs[kq * 4 + 1][m] = b4.y;
        Bs[kq * 4 + 2][m] = b4.z; Bs[kq * 4 + 3][m] = b4.w;
        __syncthreads();
#pragma unroll
        for (int kk = 0; kk < 16; kk++) {
            float a[4], b[4];
#pragma unroll
            for (int i = 0; i < 4; i++) a[i] = As[kk][ty * 4 + i];
#pragma unroll
            for (int j = 0; j < 4; j++) b[j] = Bs[kk][tx * 4 + j];
#pragma unroll
            for (int i = 0; i < 4; i++)
#pragma unroll
                for (int j = 0; j < 4; j++) acc[i][j] += a[i] * b[j];
        }
        __syncthreads();
    }
#pragma unroll
    for (int i = 0; i < 4; i++)
#pragma unroll
        for (int j = 0; j < 4; j++)
            C[(size_t)(blockIdx.x * 64 + ty * 4 + i) * WALLN + blockIdx.y * 64 + tx * 4 + j] = acc[i][j];
}

// wall[:,2048:3072] = wv; wall[:,3072:3328] = wskip;  wst[h*256+d,c] = we[d,h*256+c]
__global__ void pack_k(const float* __restrict__ wv_l, const float* __restrict__ ws_l,
                       const float* __restrict__ we_l, float* __restrict__ wall,
                       float* __restrict__ wst)
{
    int i = blockIdx.x * blockDim.x + threadIdx.x;
    if (i < DH * 1280) {
        int r = i / 1280, c = i % 1280;
        wall[(size_t)r * WALLN + OFF_V + c] =
            (c < 1024) ? wv_l[r * 1024 + c] : ws_l[r * 256 + (c - 1024)];
    }
    if (i < HC * DH) {
        int r = i >> 8, c = i & 255;
        int h = r >> 8, d = r & 255;
        wst[i] = we_l[d * 1024 + h * 256 + c];
    }
}

// ---------------- CSR build --------------------------------------------------
__global__ void zero_int_k(int* p, int n)
{
    int i = blockIdx.x * blockDim.x + threadIdx.x;
    if (i < n) p[i] = 0;
}

__global__ void deg_k(const int* __restrict__ tgt, int* __restrict__ deg)
{
    int e = blockIdx.x * blockDim.x + threadIdx.x;
    if (e < NE) atomicAdd(&deg[tgt[e]], 1);
}

__global__ __launch_bounds__(1024) void scan_k(const int* __restrict__ deg,
                                               int* __restrict__ off)
{
    __shared__ int part[1024];
    int tid = threadIdx.x;
    const int per = (NN + 1023) / 1024;
    int base = tid * per;
    int s = 0;
    for (int i = 0; i < per; i++) {
        int idx = base + i;
        if (idx < NN) s += deg[idx];
    }
    part[tid] = s;
    __syncthreads();
    for (int o = 1; o < 1024; o <<= 1) {
        int v = (tid >= o) ? part[tid - o] : 0;
        __syncthreads();
        part[tid] += v;
        __syncthreads();
    }
    int run = part[tid] - s;          // exclusive
    for (int i = 0; i < per; i++) {
        int idx = base + i;
        if (idx < NN) { off[idx] = run; run += deg[idx]; }
    }
    if (tid == 1023) off[NN] = part[1023];
}

__global__ void fillperm_k(const int* __restrict__ tgt, int* __restrict__ cur,
                           int* __restrict__ perm)
{
    int e = blockIdx.x * blockDim.x + threadIdx.x;
    if (e >= NE) return;
    int pos = atomicAdd(&cur[tgt[e]], 1);
    perm[pos] = e;
}

// ---------------- helpers ----------------------------------------------------
__global__ void fill_k(float* p, float v, int n)
{
    int i = blockIdx.x * blockDim.x + threadIdx.x;
    if (i < n) p[i] = v;
}

__global__ void embed_k(const int* __restrict__ ids, const float* __restrict__ emb,
                        float* __restrict__ x)
{
    int i = blockIdx.x * blockDim.x + threadIdx.x;
    if (i >= NN * DH) return;
    x[i] = emb[ids[i >> 8] * DH + (i & 255)];
}

// alpha[e,h] = (1/16) * ( u[t,h]·x[s] + qw[t,h]·ea[e] )
__global__ void alpha2_k(const int* __restrict__ src, const int* __restrict__ tgt,
                         const float* __restrict__ uall, const float* __restrict__ x,
                         const float* __restrict__ ea, float* __restrict__ alpha)
{
    int e = blockIdx.x;
    int h = threadIdx.y, lane = threadIdx.x;
    int s = src[e], t = tgt[e];
    const float4* up  = (const float4*)(uall + (size_t)t * WALLN + OFF_U + h * 256);
    const float4* qwp = (const float4*)(uall + (size_t)t * WALLN + OFF_QW + h * 256);
    const float4* xp  = (const float4*)(x + (size_t)s * 256);
    const float4* eap = (const float4*)(ea + (size_t)e * 256);
    float acc = 0.f;
#pragma unroll
    for (int i = 0; i < 2; i++) {
        float4 u4 = up[lane + i * 32],  x4 = xp[lane + i * 32];
        float4 q4 = qwp[lane + i * 32], e4 = eap[lane + i * 32];
        acc += u4.x * x4.x + u4.y * x4.y + u4.z * x4.z + u4.w * x4.w;
        acc += q4.x * e4.x + q4.y * e4.y + q4.z * e4.z + q4.w * e4.w;
    }
#pragma unroll
    for (int o = 16; o; o >>= 1) acc += __shfl_xor_sync(0xffffffffu, acc, o);
    if (lane == 0) alpha[e * NH + h] = acc * 0.0625f;
}

// segment softmax per (t,h): normalize alpha in place
__global__ void csr_softmax_k(const int* __restrict__ off, const int* __restrict__ perm,
                              float* __restrict__ alpha)
{
    int i = blockIdx.x * blockDim.x + threadIdx.x;
    if (i >= NN * NH) return;
    int t = i >> 2, h = i & 3;
    int b = off[t], e2 = off[t + 1];
    if (b == e2) return;
    float mx = -INFINITY;
    for (int j = b; j < e2; j++) {
        float v = alpha[perm[j] * NH + h];
        mx = fmaxf(mx, v);
    }
    float s = 0.f;
    for (int j = b; j < e2; j++) s += __expf(alpha[perm[j] * NH + h] - mx);
    float inv = 1.f / (s + 1e-16f);
    for (int j = b; j < e2; j++) {
        int e = perm[j];
        alpha[e * NH + h] = __expf(alpha[e * NH + h] - mx) * inv;
    }
}

// per target: aggVs[t,c] = sum_h sum_e a_eh v[s,h,c];  wea[t,h,d] = sum_e a_eh ea[e,d]
__global__ __launch_bounds__(256) void gather_agg_k(
    const int* __restrict__ off, const int* __restrict__ perm,
    const int* __restrict__ src, const float* __restrict__ uall,
    const float* __restrict__ ea, const float* __restrict__ alpha,
    float* __restrict__ aggVs, float* __restrict__ wea)
{
    int t = blockIdx.x;
    int tid = threadIdx.x;
    int b = off[t], e2 = off[t + 1];
    int c = tid;                      // channel for aggVs
    int idx = tid * 4;                // wea element base
    int h2 = idx >> 8, d = idx & 255;

    float accV = 0.f;
    float4 accE = make_float4(0.f, 0.f, 0.f, 0.f);

    for (int j = b; j < e2; j++) {
        int e = perm[j];
        int s = src[e];
        float4 a4 = *(const float4*)(alpha + (size_t)e * NH);
        const float* vrow = uall + (size_t)s * WALLN + OFF_V;
        accV += a4.x * vrow[c] + a4.y * vrow[256 + c]
              + a4.z * vrow[512 + c] + a4.w * vrow[768 + c];
        float ah = (h2 == 0) ? a4.x : (h2 == 1) ? a4.y : (h2 == 2) ? a4.z : a4.w;
        float4 e4 = *(const float4*)(ea + (size_t)e * 256 + d);
        accE.x += ah * e4.x; accE.y += ah * e4.y;
        accE.z += ah * e4.z; accE.w += ah * e4.w;
    }
    aggVs[(size_t)t * DH + c] = accV;
    *(float4*)(wea + (size_t)t * HC + idx) = accE;
}

// x = 0.25*(aggVs + aggE) + skip  (skip lives in uall)
__global__ void combine3_k(const float* __restrict__ aggVs, const float* __restrict__ aggE,
                           const float* __restrict__ uall, float* __restrict__ x)
{
    int i = blockIdx.x * blockDim.x + threadIdx.x;
    if (i >= NN * DH) return;
    int n = i >> 8, c = i & 255;
    x[i] = 0.25f * (aggVs[i] + aggE[i]) + uall[(size_t)n * WALLN + OFF_SKIP + c];
}

__device__ __forceinline__ void atomicMaxF(float* addr, float v)
{
    if (v >= 0.f) atomicMax((int*)addr, __float_as_int(v));
    else          atomicMin((unsigned int*)addr, __float_as_uint(v));
}

__global__ void cnt_k(const int* __restrict__ batch, float* __restrict__ cnt)
{
    int n = blockIdx.x * blockDim.x + threadIdx.x;
    if (n < NN) atomicAdd(&cnt[batch[n]], 1.f);
}

__global__ void pool_init_max_k(float* __restrict__ feat)
{
    int i = blockIdx.x * blockDim.x + threadIdx.x;
    if (i >= NB * 256) return;
    feat[(i >> 8) * FEATD + 256 + (i & 255)] = __int_as_float(0xff800000u);
}

__global__ void pool_k(const int* __restrict__ batch, const float* __restrict__ x,
                       float* __restrict__ feat)
{
    int i = blockIdx.x * blockDim.x + threadIdx.x;
    if (i >= NN * DH) return;
    int n = i >> 8, c = i & 255;
    int b = batch[n];
    float v = x[i];
    atomicAdd(&feat[b * FEATD + 512 + c], v);
    atomicMaxF(&feat[b * FEATD + 256 + c], v);
}

__global__ void meanpool_k(float* __restrict__ feat, const float* __restrict__ cnt)
{
    int i = blockIdx.x * blockDim.x + threadIdx.x;
    if (i >= NB * 256) return;
    int b = i >> 8, c = i & 255;
    feat[b * FEATD + c] = feat[b * FEATD + 512 + c] / cnt[b];
}

// ---------------- launch -----------------------------------------------------
static inline dim3 g128(int M, int Nn) { return dim3((M + 127) / 128, (Nn + 127) / 128); }

extern "C" void kernel_launch(void* const* d_in, const int* in_sizes, int n_in,
                              void* d_out, int out_size)
{
    const int*   x_ids    = (const int*)  d_in[0];
    const int*   eidx     = (const int*)  d_in[1];
    const int*   batch    = (const int*)  d_in[2];
    const float* edge_attr= (const float*)d_in[3];
    const float* energies = (const float*)d_in[4];
    const float* node_emb = (const float*)d_in[5];
    const float* ew1      = (const float*)d_in[6];
    const float* eb1      = (const float*)d_in[7];
    const float* ew2      = (const float*)d_in[8];
    const float* eb2      = (const float*)d_in[9];
    const float* wq       = (const float*)d_in[10];
    const float* wk       = (const float*)d_in[11];
    const float* wv       = (const float*)d_in[12];
    const float* we       = (const float*)d_in[13];
    const float* wskip    = (const float*)d_in[14];
    const float* fce_w1   = (const float*)d_in[15];
    const float* fce_b1   = (const float*)d_in[16];
    const float* fce_w2   = (const float*)d_in[17];
    const float* fce_b2   = (const float*)d_in[18];
    const float* fc_w1    = (const float*)d_in[19];
    const float* fc_b1    = (const float*)d_in[20];
    const float* fc_w2    = (const float*)d_in[21];
    const float* fc_b2    = (const float*)d_in[22];
    float* out = (float*)d_out;

    const int* src = eidx;
    const int* tgt = eidx + NE;

    float *x, *h, *ea, *wall, *wst, *uall, *alpha, *aggVs, *wea, *aggE,
          *feat, *cnt, *en1, *fc1;
    int *deg, *off, *cur, *perm;
    cudaGetSymbolAddress((void**)&x,     g_x);
    cudaGetSymbolAddress((void**)&h,     g_h);
    cudaGetSymbolAddress((void**)&ea,    g_ea);
    cudaGetSymbolAddress((void**)&wall,  g_wall);
    cudaGetSymbolAddress((void**)&wst,   g_wst);
    cudaGetSymbolAddress((void**)&uall,  g_uall);
    cudaGetSymbolAddress((void**)&alpha, g_alpha);
    cudaGetSymbolAddress((void**)&aggVs, g_aggVs);
    cudaGetSymbolAddress((void**)&wea,   g_wea);
    cudaGetSymbolAddress((void**)&aggE,  g_aggE);
    cudaGetSymbolAddress((void**)&feat,  g_feat);
    cudaGetSymbolAddress((void**)&cnt,   g_cnt);
    cudaGetSymbolAddress((void**)&en1,   g_en1);
    cudaGetSymbolAddress((void**)&fc1,   g_fc1);
    cudaGetSymbolAddress((void**)&deg,   g_deg);
    cudaGetSymbolAddress((void**)&off,   g_off);
    cudaGetSymbolAddress((void**)&cur,   g_cur);
    cudaGetSymbolAddress((void**)&perm,  g_perm);

    // CSR build (once per call; edge_index constant)
    zero_int_k<<<(NN + 255) / 256, 256>>>(deg, NN);
    deg_k<<<(NE + 255) / 256, 256>>>(tgt, deg);
    scan_k<<<1, 1024>>>(deg, off);
    cudaMemcpyAsync(cur, off, NN * sizeof(int), cudaMemcpyDeviceToDevice);
    fillperm_k<<<(NE + 255) / 256, 256>>>(tgt, cur, perm);

    // node embedding
    embed_k<<<(NN * DH + 255) / 256, 256>>>(x_ids, node_emb, x);

    // edge MLP
    sgemm_k<<<g128(NE, 128), 256>>>(edge_attr, ew1, eb1, h, NE, 14, 128, 128, 1);
    gemm2<<<g128(NE, 256), 256>>>(h, ew2, eb2, ea, NE, 128, 256, 128, 256, 256, 0);

    for (int l = 0; l < 3; l++) {
        const float* wql = wq + (size_t)l * DH * HC;
        const float* wkl = wk + (size_t)l * DH * HC;
        const float* wvl = wv + (size_t)l * DH * HC;
        const float* wel = we + (size_t)l * DH * HC;
        const float* wsl = wskip + (size_t)l * DH * DH;

        wprep_k<<<dim3(4, 4, 8), 256>>>(wql, wkl, wel, wall);
        pack_k<<<(DH * 1280 + 255) / 256, 256>>>(wvl, wsl, wel, wall, wst);

        // single fused node GEMM: uall = x @ wall
        gemm2<<<g128(NN, WALLN), 256>>>(x, wall, nullptr, uall,
                                        NN, 256, WALLN, 256, WALLN, WALLN, 0);

        // attention logits + CSR softmax
        alpha2_k<<<NE, dim3(32, 4)>>>(src, tgt, uall, x, ea, alpha);
        csr_softmax_k<<<(NN * NH + 255) / 256, 256>>>(off, perm, alpha);

        // gather-based aggregation (no atomics)
        gather_agg_k<<<NN, 256>>>(off, perm, src, uall, ea, alpha, aggVs, wea);

        // edge contribution via node GEMM, then combine
        gemm2<<<g128(NN, DH), 256>>>(wea, wst, nullptr, aggE,
                                     NN, 1024, 256, 1024, 256, 256, 0);
        combine3_k<<<(NN * DH + 255) / 256, 256>>>(aggVs, aggE, uall, x);
    }

    // pooling
    fill_k<<<(NB * FEATD + 255) / 256, 256>>>(feat, 0.f, NB * FEATD);
    pool_init_max_k<<<(NB * 256 + 255) / 256, 256>>>(feat);
    fill_k<<<1, NB>>>(cnt, 0.f, NB);
    cnt_k<<<(NN + 255) / 256, 256>>>(batch, cnt);
    pool_k<<<(NN * DH + 255) / 256, 256>>>(batch, x, feat);
    meanpool_k<<<(NB * 256 + 255) / 256, 256>>>(feat, cnt);

    // energies MLP
    sgemm_k<<<g128(NB, 256), 256>>>(energies, fce_w1, fce_b1, en1, NB, 201, 256, 256, 1);
    sgemm_k<<<g128(NB, 128), 256>>>(en1, fce_w2, fce_b2, feat + 768, NB, 256, 128, FEATD, 0);

    // final MLP
    sgemm_k<<<g128(NB, 1024), 256>>>(feat, fc_w1, fc_b1, fc1, NB, FEATD, 1024, 1024, 1);
    sgemm_k<<<g128(NB, 804),  256>>>(fc1,  fc_w2, fc_b2, out, NB, 1024,  804,  804,  0);
}

// round 5
// speedup vs baseline: 3.6676x; 1.7364x over previous
#include <cuda_runtime.h>
#include <math.h>
#include <stdint.h>

#define NN   10000
#define NE   80000
#define NB   64
#define NH   4
#define DH   256
#define HC   1024
#define FEATD 896

// uall column layout: [u(1024) | qw(1024) | v(1024) | skip(256)]
#define WALLN 3328
#define OFF_U    0
#define OFF_QW   1024
#define OFF_V    2048
#define OFF_SKIP 3072

// ---------------- scratch ----------------------------------------------------
__device__ float g_x    [NN * DH];
__device__ float g_h    [NE * 128];
__device__ float g_ea   [NE * DH];
__device__ float g_wall [DH * WALLN];
__device__ float g_wst  [HC * DH];
__device__ float g_uall [NN * WALLN];
__device__ float g_alpha[NE * NH];
__device__ float g_aggVs[NN * DH];
__device__ float g_wea  [NN * HC];
__device__ float g_aggE [NN * DH];
__device__ float g_feat [NB * FEATD];
__device__ float g_cnt  [NB];
__device__ float g_en1  [NB * 256];
__device__ float g_fc1  [NB * 1024];
__device__ int   g_deg  [NN];
__device__ int   g_off  [NN + 1];
__device__ int   g_cur  [NN];
__device__ int   g_perm [NE];

// ---------------- tf32 helpers -----------------------------------------------
__device__ __forceinline__ float f2tf32(float f)
{
    uint32_t u;
    asm("cvt.rna.tf32.f32 %0, %1;" : "=r"(u) : "f"(f));
    return __uint_as_float(u);
}

__device__ __forceinline__ void mma168(float& d0, float& d1, float& d2, float& d3,
                                       uint32_t a0, uint32_t a1, uint32_t a2, uint32_t a3,
                                       uint32_t b0, uint32_t b1)
{
    asm volatile(
        "mma.sync.aligned.m16n8k8.row.col.f32.tf32.tf32.f32 "
        "{%0,%1,%2,%3}, {%4,%5,%6,%7}, {%8,%9}, {%0,%1,%2,%3};"
        : "+f"(d0), "+f"(d1), "+f"(d2), "+f"(d3)
        : "r"(a0), "r"(a1), "r"(a2), "r"(a3), "r"(b0), "r"(b1));
}

// ---------------- tgemm: tf32 tensor-core GEMM -------------------------------
// C[M,N] = act(A[M,K] @ B[K,N] + bias). Requires K%16==0, N%128==0.
// 128x128x16 tiles, 8 warps (4x2), warp tile 32x64, double-buffered.
__global__ __launch_bounds__(256) void tgemm(
    const float* __restrict__ A, const float* __restrict__ B,
    const float* __restrict__ bias, float* __restrict__ C,
    int M, int K, int N, int lda, int ldb, int ldc, int flags)
{
    __shared__ float As[2][128][20];   // pad 20 -> conflict-free frag loads
    __shared__ float Bs[2][16][132];   // pad 132 -> conflict-free frag loads

    const int tid    = threadIdx.x;
    const int lane   = tid & 31;
    const int warp   = tid >> 5;
    const int warpM  = warp >> 1;          // 0..3
    const int warpN  = warp & 1;           // 0..1
    const int rowW   = warpM * 32;
    const int colW   = warpN * 64;
    const int gid    = lane >> 2;          // groupID 0..7
    const int tig    = lane & 3;           // threadID_in_group
    const int row0   = blockIdx.x * 128;
    const int col0   = blockIdx.y * 128;
    const int nT     = K / 16;

    float4 aReg[2], bReg[2];
    float acc[2][8][4];
#pragma unroll
    for (int mi = 0; mi < 2; mi++)
#pragma unroll
        for (int ni = 0; ni < 8; ni++)
#pragma unroll
            for (int r = 0; r < 4; r++) acc[mi][ni][r] = 0.f;

    auto fetch = [&](int kt) {
        int k0 = kt * 16;
#pragma unroll
        for (int i = 0; i < 2; i++) {
            int r = (tid >> 2) + 64 * i;         // 0..127
            int c = (tid & 3) * 4;
            int gr = row0 + r;
            aReg[i] = (gr < M) ? *(const float4*)(A + (size_t)gr * lda + k0 + c)
                               : make_float4(0.f, 0.f, 0.f, 0.f);
        }
#pragma unroll
        for (int i = 0; i < 2; i++) {
            int r = (tid >> 5) + 8 * i;          // 0..15
            int c = (tid & 31) * 4;
            bReg[i] = *(const float4*)(B + (size_t)(k0 + r) * ldb + col0 + c);
        }
    };
    auto store = [&](int buf) {
#pragma unroll
        for (int i = 0; i < 2; i++) {
            int r = (tid >> 2) + 64 * i;
            int c = (tid & 3) * 4;
            As[buf][r][c + 0] = f2tf32(aReg[i].x);
            As[buf][r][c + 1] = f2tf32(aReg[i].y);
            As[buf][r][c + 2] = f2tf32(aReg[i].z);
            As[buf][r][c + 3] = f2tf32(aReg[i].w);
        }
#pragma unroll
        for (int i = 0; i < 2; i++) {
            int r = (tid >> 5) + 8 * i;
            int c = (tid & 31) * 4;
            Bs[buf][r][c + 0] = f2tf32(bReg[i].x);
            Bs[buf][r][c + 1] = f2tf32(bReg[i].y);
            Bs[buf][r][c + 2] = f2tf32(bReg[i].z);
            Bs[buf][r][c + 3] = f2tf32(bReg[i].w);
        }
    };

    fetch(0); store(0);
    if (nT > 1) fetch(1);
    __syncthreads();

    for (int t = 0; t < nT; t++) {
        int cur = t & 1;
#pragma unroll
        for (int k8 = 0; k8 < 16; k8 += 8) {
            uint32_t af[2][4];
#pragma unroll
            for (int mi = 0; mi < 2; mi++) {
                int r = rowW + mi * 16 + gid;
                af[mi][0] = __float_as_uint(As[cur][r    ][k8 + tig]);
                af[mi][1] = __float_as_uint(As[cur][r + 8][k8 + tig]);
                af[mi][2] = __float_as_uint(As[cur][r    ][k8 + tig + 4]);
                af[mi][3] = __float_as_uint(As[cur][r + 8][k8 + tig + 4]);
            }
            uint32_t bf[8][2];
#pragma unroll
            for (int ni = 0; ni < 8; ni++) {
                int c = colW + ni * 8 + gid;
                bf[ni][0] = __float_as_uint(Bs[cur][k8 + tig    ][c]);
                bf[ni][1] = __float_as_uint(Bs[cur][k8 + tig + 4][c]);
            }
#pragma unroll
            for (int mi = 0; mi < 2; mi++)
#pragma unroll
                for (int ni = 0; ni < 8; ni++)
                    mma168(acc[mi][ni][0], acc[mi][ni][1], acc[mi][ni][2], acc[mi][ni][3],
                           af[mi][0], af[mi][1], af[mi][2], af[mi][3],
                           bf[ni][0], bf[ni][1]);
        }
        if (t + 1 < nT) store((t + 1) & 1);
        if (t + 2 < nT) fetch(t + 2);
        __syncthreads();
    }

#pragma unroll
    for (int mi = 0; mi < 2; mi++) {
        int r0 = row0 + rowW + mi * 16 + gid;
#pragma unroll
        for (int ni = 0; ni < 8; ni++) {
            int c0 = col0 + colW + ni * 8 + tig * 2;
#pragma unroll
            for (int rr = 0; rr < 2; rr++) {
                int gr = r0 + rr * 8;
                if (gr >= M) continue;
#pragma unroll
                for (int cc = 0; cc < 2; cc++) {
                    int gc = c0 + cc;
                    float vv = acc[mi][ni][rr * 2 + cc];
                    if (bias) vv += bias[gc];
                    if (flags & 1) vv = vv > 0.f ? vv : 0.01f * vv;
                    C[(size_t)gr * ldc + gc] = vv;
                }
            }
        }
    }
}

// ---------------- legacy sgemm (ragged K / tiny M) ---------------------------
__global__ void sgemm_k(const float* __restrict__ A, const float* __restrict__ B,
                        const float* __restrict__ bias, float* __restrict__ C,
                        int M, int K, int Nn, int ldc, int act)
{
    __shared__ float As[8][128];
    __shared__ float Bs[8][128];
    const int tid = threadIdx.x;
    const int row0 = blockIdx.x * 128;
    const int col0 = blockIdx.y * 128;
    const int ty = tid >> 4;
    const int tx = tid & 15;

    float acc[8][8];
#pragma unroll
    for (int i = 0; i < 8; i++)
#pragma unroll
        for (int j = 0; j < 8; j++) acc[i][j] = 0.f;

    for (int k0 = 0; k0 < K; k0 += 8) {
#pragma unroll
        for (int i = 0; i < 4; i++) {
            int idx = tid + i * 256;
            int r = idx >> 3, c = idx & 7;
            int gr = row0 + r, gc = k0 + c;
            As[c][r] = (gr < M && gc < K) ? A[(size_t)gr * K + gc] : 0.f;
        }
#pragma unroll
        for (int i = 0; i < 4; i++) {
            int idx = tid + i * 256;
            int r = idx >> 7, c = idx & 127;
            int gr = k0 + r, gc = col0 + c;
            Bs[r][c] = (gr < K && gc < Nn) ? B[(size_t)gr * Nn + gc] : 0.f;
        }
        __syncthreads();
#pragma unroll
        for (int kk = 0; kk < 8; kk++) {
            float a[8], b[8];
#pragma unroll
            for (int i = 0; i < 8; i++) a[i] = As[kk][ty * 8 + i];
#pragma unroll
            for (int j = 0; j < 8; j++) b[j] = Bs[kk][tx * 8 + j];
#pragma unroll
            for (int i = 0; i < 8; i++)
#pragma unroll
                for (int j = 0; j < 8; j++) acc[i][j] += a[i] * b[j];
        }
        __syncthreads();
    }

#pragma unroll
    for (int i = 0; i < 8; i++) {
        int gr = row0 + ty * 8 + i;
        if (gr >= M) continue;
#pragma unroll
        for (int j = 0; j < 8; j++) {
            int gc = col0 + tx * 8 + j;
            if (gc >= Nn) continue;
            float v = acc[i][j];
            if (bias) v += bias[gc];
            if (act)  v = v > 0.f ? v : 0.01f * v;
            C[(size_t)gr * ldc + gc] = v;
        }
    }
}

// ---------------- weight prep: Wqk_h=Wq_h@Wk_h^T, Wqe_h=Wq_h@We_h^T ----------
__global__ __launch_bounds__(256) void wprep_k(const float* __restrict__ wq_l,
                                               const float* __restrict__ wk_l,
                                               const float* __restrict__ we_l,
                                               float* __restrict__ wall)
{
    int z = blockIdx.z;
    int h = z >> 1, which = z & 1;
    const float* A = wq_l + h * 256;
    const float* B = (which ? we_l : wk_l) + h * 256;
    float* C = wall + (which ? OFF_QW : OFF_U) + h * 256;

    __shared__ float As[16][64];
    __shared__ float Bs[16][64];
    int tid = threadIdx.x;
    int ty = tid >> 4, tx = tid & 15;
    float acc[4][4];
#pragma unroll
    for (int i = 0; i < 4; i++)
#pragma unroll
        for (int j = 0; j < 4; j++) acc[i][j] = 0.f;

    for (int k0 = 0; k0 < 256; k0 += 16) {
        int m = tid >> 2, kq = tid & 3;
        float4 a4 = *(const float4*)(A + (size_t)(blockIdx.x * 64 + m) * 1024 + k0 + kq * 4);
        As[kq * 4 + 0][m] = a4.x; As[kq * 4 + 1][m] = a4.y;
        As[kq * 4 + 2][m] = a4.z; As[kq * 4 + 3][m] = a4.w;
        float4 b4 = *(const float4*)(B + (size_t)(blockIdx.y * 64 + m) * 1024 + k0 + kq * 4);
        Bs[kq * 4 + 0][m] = b4.x; Bs[kq * 4 + 1][m] = b4.y;
        Bs[kq * 4 + 2][m] = b4.z; Bs[kq * 4 + 3][m] = b4.w;
        __syncthreads();
#pragma unroll
        for (int kk = 0; kk < 16; kk++) {
            float a[4], b[4];
#pragma unroll
            for (int i = 0; i < 4; i++) a[i] = As[kk][ty * 4 + i];
#pragma unroll
            for (int j = 0; j < 4; j++) b[j] = Bs[kk][tx * 4 + j];
#pragma unroll
            for (int i = 0; i < 4; i++)
#pragma unroll
                for (int j = 0; j < 4; j++) acc[i][j] += a[i] * b[j];
        }
        __syncthreads();
    }
#pragma unroll
    for (int i = 0; i < 4; i++)
#pragma unroll
        for (int j = 0; j < 4; j++)
            C[(size_t)(blockIdx.x * 64 + ty * 4 + i) * WALLN + blockIdx.y * 64 + tx * 4 + j] = acc[i][j];
}

// wall[:,2048:3072]=wv; wall[:,3072:3328]=wskip;  wst[h*256+d,c]=we[d,h*256+c]
__global__ void pack_k(const float* __restrict__ wv_l, const float* __restrict__ ws_l,
                       const float* __restrict__ we_l, float* __restrict__ wall,
                       float* __restrict__ wst)
{
    int i = blockIdx.x * blockDim.x + threadIdx.x;
    if (i < DH * 1280) {
        int r = i / 1280, c = i % 1280;
        wall[(size_t)r * WALLN + OFF_V + c] =
            (c < 1024) ? wv_l[r * 1024 + c] : ws_l[r * 256 + (c - 1024)];
    }
    if (i < HC * DH) {
        int r = i >> 8, c = i & 255;
        int h = r >> 8, d = r & 255;
        wst[i] = we_l[d * 1024 + h * 256 + c];
    }
}

// ---------------- CSR build --------------------------------------------------
__global__ void zero_int_k(int* p, int n)
{
    int i = blockIdx.x * blockDim.x + threadIdx.x;
    if (i < n) p[i] = 0;
}

__global__ void deg_k(const int* __restrict__ tgt, int* __restrict__ deg)
{
    int e = blockIdx.x * blockDim.x + threadIdx.x;
    if (e < NE) atomicAdd(&deg[tgt[e]], 1);
}

__global__ __launch_bounds__(1024) void scan_k(const int* __restrict__ deg,
                                               int* __restrict__ off)
{
    __shared__ int part[1024];
    int tid = threadIdx.x;
    const int per = (NN + 1023) / 1024;
    int base = tid * per;
    int s = 0;
    for (int i = 0; i < per; i++) {
        int idx = base + i;
        if (idx < NN) s += deg[idx];
    }
    part[tid] = s;
    __syncthreads();
    for (int o = 1; o < 1024; o <<= 1) {
        int v = (tid >= o) ? part[tid - o] : 0;
        __syncthreads();
        part[tid] += v;
        __syncthreads();
    }
    int run = part[tid] - s;
    for (int i = 0; i < per; i++) {
        int idx = base + i;
        if (idx < NN) { off[idx] = run; run += deg[idx]; }
    }
    if (tid == 1023) off[NN] = part[1023];
}

__global__ void fillperm_k(const int* __restrict__ tgt, int* __restrict__ cur,
                           int* __restrict__ perm)
{
    int e = blockIdx.x * blockDim.x + threadIdx.x;
    if (e >= NE) return;
    int pos = atomicAdd(&cur[tgt[e]], 1);
    perm[pos] = e;
}

// ---------------- helpers ----------------------------------------------------
__global__ void fill_k(float* p, float v, int n)
{
    int i = blockIdx.x * blockDim.x + threadIdx.x;
    if (i < n) p[i] = v;
}

__global__ void embed_k(const int* __restrict__ ids, const float* __restrict__ emb,
                        float* __restrict__ x)
{
    int i = blockIdx.x * blockDim.x + threadIdx.x;
    if (i >= NN * DH) return;
    x[i] = emb[ids[i >> 8] * DH + (i & 255)];
}

// alpha[e,h] = (1/16) * ( u[t,h]·x[s] + qw[t,h]·ea[e] )
__global__ void alpha2_k(const int* __restrict__ src, const int* __restrict__ tgt,
                         const float* __restrict__ uall, const float* __restrict__ x,
                         const float* __restrict__ ea, float* __restrict__ alpha)
{
    int e = blockIdx.x;
    int h = threadIdx.y, lane = threadIdx.x;
    int s = src[e], t = tgt[e];
    const float4* up  = (const float4*)(uall + (size_t)t * WALLN + OFF_U + h * 256);
    const float4* qwp = (const float4*)(uall + (size_t)t * WALLN + OFF_QW + h * 256);
    const float4* xp  = (const float4*)(x + (size_t)s * 256);
    const float4* eap = (const float4*)(ea + (size_t)e * 256);
    float acc = 0.f;
#pragma unroll
    for (int i = 0; i < 2; i++) {
        float4 u4 = up[lane + i * 32],  x4 = xp[lane + i * 32];
        float4 q4 = qwp[lane + i * 32], e4 = eap[lane + i * 32];
        acc += u4.x * x4.x + u4.y * x4.y + u4.z * x4.z + u4.w * x4.w;
        acc += q4.x * e4.x + q4.y * e4.y + q4.z * e4.z + q4.w * e4.w;
    }
#pragma unroll
    for (int o = 16; o; o >>= 1) acc += __shfl_xor_sync(0xffffffffu, acc, o);
    if (lane == 0) alpha[e * NH + h] = acc * 0.0625f;
}

// segment softmax per (t,h): normalize alpha in place
__global__ void csr_softmax_k(const int* __restrict__ off, const int* __restrict__ perm,
                              float* __restrict__ alpha)
{
    int i = blockIdx.x * blockDim.x + threadIdx.x;
    if (i >= NN * NH) return;
    int t = i >> 2, h = i & 3;
    int b = off[t], e2 = off[t + 1];
    if (b == e2) return;
    float mx = -INFINITY;
    for (int j = b; j < e2; j++) {
        float v = alpha[perm[j] * NH + h];
        mx = fmaxf(mx, v);
    }
    float s = 0.f;
    for (int j = b; j < e2; j++) s += __expf(alpha[perm[j] * NH + h] - mx);
    float inv = 1.f / (s + 1e-16f);
    for (int j = b; j < e2; j++) {
        int e = perm[j];
        alpha[e * NH + h] = __expf(alpha[e * NH + h] - mx) * inv;
    }
}

// per target: aggVs[t,c] = sum_h sum_e a_eh v[s,h,c];  wea[t,h,d] = sum_e a_eh ea[e,d]
__global__ __launch_bounds__(256) void gather_agg_k(
    const int* __restrict__ off, const int* __restrict__ perm,
    const int* __restrict__ src, const float* __restrict__ uall,
    const float* __restrict__ ea, const float* __restrict__ alpha,
    float* __restrict__ aggVs, float* __restrict__ wea)
{
    int t = blockIdx.x;
    int tid = threadIdx.x;
    int b = off[t], e2 = off[t + 1];
    int c = tid;
    int idx = tid * 4;
    int h2 = idx >> 8, d = idx & 255;

    float accV = 0.f;
    float4 accE = make_float4(0.f, 0.f, 0.f, 0.f);

    for (int j = b; j < e2; j++) {
        int e = perm[j];
        int s = src[e];
        float4 a4 = *(const float4*)(alpha + (size_t)e * NH);
        const float* vrow = uall + (size_t)s * WALLN + OFF_V;
        accV += a4.x * vrow[c] + a4.y * vrow[256 + c]
              + a4.z * vrow[512 + c] + a4.w * vrow[768 + c];
        float ah = (h2 == 0) ? a4.x : (h2 == 1) ? a4.y : (h2 == 2) ? a4.z : a4.w;
        float4 e4 = *(const float4*)(ea + (size_t)e * 256 + d);
        accE.x += ah * e4.x; accE.y += ah * e4.y;
        accE.z += ah * e4.z; accE.w += ah * e4.w;
    }
    aggVs[(size_t)t * DH + c] = accV;
    *(float4*)(wea + (size_t)t * HC + idx) = accE;
}

// x = 0.25*(aggVs + aggE) + skip  (skip lives in uall)
__global__ void combine3_k(const float* __restrict__ aggVs, const float* __restrict__ aggE,
                           const float* __restrict__ uall, float* __restrict__ x)
{
    int i = blockIdx.x * blockDim.x + threadIdx.x;
    if (i >= NN * DH) return;
    int n = i >> 8, c = i & 255;
    x[i] = 0.25f * (aggVs[i] + aggE[i]) + uall[(size_t)n * WALLN + OFF_SKIP + c];
}

__device__ __forceinline__ void atomicMaxF(float* addr, float v)
{
    if (v >= 0.f) atomicMax((int*)addr, __float_as_int(v));
    else          atomicMin((unsigned int*)addr, __float_as_uint(v));
}

__global__ void cnt_k(const int* __restrict__ batch, float* __restrict__ cnt)
{
    int n = blockIdx.x * blockDim.x + threadIdx.x;
    if (n < NN) atomicAdd(&cnt[batch[n]], 1.f);
}

__global__ void pool_init_max_k(float* __restrict__ feat)
{
    int i = blockIdx.x * blockDim.x + threadIdx.x;
    if (i >= NB * 256) return;
    feat[(i >> 8) * FEATD + 256 + (i & 255)] = __int_as_float(0xff800000u);
}

__global__ void pool_k(const int* __restrict__ batch, const float* __restrict__ x,
                       float* __restrict__ feat)
{
    int i = blockIdx.x * blockDim.x + threadIdx.x;
    if (i >= NN * DH) return;
    int n = i >> 8, c = i & 255;
    int b = batch[n];
    float v = x[i];
    atomicAdd(&feat[b * FEATD + 512 + c], v);
    atomicMaxF(&feat[b * FEATD + 256 + c], v);
}

__global__ void meanpool_k(float* __restrict__ feat, const float* __restrict__ cnt)
{
    int i = blockIdx.x * blockDim.x + threadIdx.x;
    if (i >= NB * 256) return;
    int b = i >> 8, c = i & 255;
    feat[b * FEATD + c] = feat[b * FEATD + 512 + c] / cnt[b];
}

// ---------------- launch -----------------------------------------------------
static inline dim3 g128(int M, int Nn) { return dim3((M + 127) / 128, (Nn + 127) / 128); }

extern "C" void kernel_launch(void* const* d_in, const int* in_sizes, int n_in,
                              void* d_out, int out_size)
{
    const int*   x_ids    = (const int*)  d_in[0];
    const int*   eidx     = (const int*)  d_in[1];
    const int*   batch    = (const int*)  d_in[2];
    const float* edge_attr= (const float*)d_in[3];
    const float* energies = (const float*)d_in[4];
    const float* node_emb = (const float*)d_in[5];
    const float* ew1      = (const float*)d_in[6];
    const float* eb1      = (const float*)d_in[7];
    const float* ew2      = (const float*)d_in[8];
    const float* eb2      = (const float*)d_in[9];
    const float* wq       = (const float*)d_in[10];
    const float* wk       = (const float*)d_in[11];
    const float* wv       = (const float*)d_in[12];
    const float* we       = (const float*)d_in[13];
    const float* wskip    = (const float*)d_in[14];
    const float* fce_w1   = (const float*)d_in[15];
    const float* fce_b1   = (const float*)d_in[16];
    const float* fce_w2   = (const float*)d_in[17];
    const float* fce_b2   = (const float*)d_in[18];
    const float* fc_w1    = (const float*)d_in[19];
    const float* fc_b1    = (const float*)d_in[20];
    const float* fc_w2    = (const float*)d_in[21];
    const float* fc_b2    = (const float*)d_in[22];
    float* out = (float*)d_out;

    const int* src = eidx;
    const int* tgt = eidx + NE;

    float *x, *h, *ea, *wall, *wst, *uall, *alpha, *aggVs, *wea, *aggE,
          *feat, *cnt, *en1, *fc1;
    int *deg, *off, *cur, *perm;
    cudaGetSymbolAddress((void**)&x,     g_x);
    cudaGetSymbolAddress((void**)&h,     g_h);
    cudaGetSymbolAddress((void**)&ea,    g_ea);
    cudaGetSymbolAddress((void**)&wall,  g_wall);
    cudaGetSymbolAddress((void**)&wst,   g_wst);
    cudaGetSymbolAddress((void**)&uall,  g_uall);
    cudaGetSymbolAddress((void**)&alpha, g_alpha);
    cudaGetSymbolAddress((void**)&aggVs, g_aggVs);
    cudaGetSymbolAddress((void**)&wea,   g_wea);
    cudaGetSymbolAddress((void**)&aggE,  g_aggE);
    cudaGetSymbolAddress((void**)&feat,  g_feat);
    cudaGetSymbolAddress((void**)&cnt,   g_cnt);
    cudaGetSymbolAddress((void**)&en1,   g_en1);
    cudaGetSymbolAddress((void**)&fc1,   g_fc1);
    cudaGetSymbolAddress((void**)&deg,   g_deg);
    cudaGetSymbolAddress((void**)&off,   g_off);
    cudaGetSymbolAddress((void**)&cur,   g_cur);
    cudaGetSymbolAddress((void**)&perm,  g_perm);

    // CSR build
    zero_int_k<<<(NN + 255) / 256, 256>>>(deg, NN);
    deg_k<<<(NE + 255) / 256, 256>>>(tgt, deg);
    scan_k<<<1, 1024>>>(deg, off);
    cudaMemcpyAsync(cur, off, NN * sizeof(int), cudaMemcpyDeviceToDevice);
    fillperm_k<<<(NE + 255) / 256, 256>>>(tgt, cur, perm);

    // node embedding
    embed_k<<<(NN * DH + 255) / 256, 256>>>(x_ids, node_emb, x);

    // edge MLP
    sgemm_k<<<g128(NE, 128), 256>>>(edge_attr, ew1, eb1, h, NE, 14, 128, 128, 1);
    tgemm<<<g128(NE, 256), 256>>>(h, ew2, eb2, ea, NE, 128, 256, 128, 256, 256, 0);

    for (int l = 0; l < 3; l++) {
        const float* wql = wq + (size_t)l * DH * HC;
        const float* wkl = wk + (size_t)l * DH * HC;
        const float* wvl = wv + (size_t)l * DH * HC;
        const float* wel = we + (size_t)l * DH * HC;
        const float* wsl = wskip + (size_t)l * DH * DH;

        wprep_k<<<dim3(4, 4, 8), 256>>>(wql, wkl, wel, wall);
        pack_k<<<(DH * 1280 + 255) / 256, 256>>>(wvl, wsl, wel, wall, wst);

        // single fused node GEMM on tensor cores: uall = x @ wall
        tgemm<<<g128(NN, WALLN), 256>>>(x, wall, nullptr, uall,
                                        NN, 256, WALLN, 256, WALLN, WALLN, 0);

        // attention logits + CSR softmax
        alpha2_k<<<NE, dim3(32, 4)>>>(src, tgt, uall, x, ea, alpha);
        csr_softmax_k<<<(NN * NH + 255) / 256, 256>>>(off, perm, alpha);

        // gather-based aggregation (no atomics)
        gather_agg_k<<<NN, 256>>>(off, perm, src, uall, ea, alpha, aggVs, wea);

        // edge contribution via node GEMM on tensor cores, then combine
        tgemm<<<g128(NN, DH), 256>>>(wea, wst, nullptr, aggE,
                                     NN, 1024, 256, 1024, 256, 256, 0);
        combine3_k<<<(NN * DH + 255) / 256, 256>>>(aggVs, aggE, uall, x);
    }

    // pooling
    fill_k<<<(NB * FEATD + 255) / 256, 256>>>(feat, 0.f, NB * FEATD);
    pool_init_max_k<<<(NB * 256 + 255) / 256, 256>>>(feat);
    fill_k<<<1, NB>>>(cnt, 0.f, NB);
    cnt_k<<<(NN + 255) / 256, 256>>>(batch, cnt);
    pool_k<<<(NN * DH + 255) / 256, 256>>>(batch, x, feat);
    meanpool_k<<<(NB * 256 + 255) / 256, 256>>>(feat, cnt);

    // energies MLP
    sgemm_k<<<g128(NB, 256), 256>>>(energies, fce_w1, fce_b1, en1, NB, 201, 256, 256, 1);
    sgemm_k<<<g128(NB, 128), 256>>>(en1, fce_w2, fce_b2, feat + 768, NB, 256, 128, FEATD, 0);

    // final MLP
    sgemm_k<<<g128(NB, 1024), 256>>>(feat, fc_w1, fc_b1, fc1, NB, FEATD, 1024, 1024, 1);
    sgemm_k<<<g128(NB, 804),  256>>>(fc1,  fc_w2, fc_b2, out, NB, 1024,  804,  804,  0);
}

// round 6
// speedup vs baseline: 4.0306x; 1.0990x over previous
#include <cuda_runtime.h>
#include <math.h>
#include <stdint.h>

#define NN   10000
#define NE   80000
#define NB   64
#define NH   4
#define DH   256
#define HC   1024
#define FEATD 896

// uall column layout: [u(1024) | qw(1024) | v(1024) | skip(256)]
#define WALLN 3328
#define OFF_U    0
#define OFF_QW   1024
#define OFF_V    2048
#define OFF_SKIP 3072

#define CAP 128   // per-target smem edge capacity in edge_fused_k

// ---------------- scratch ----------------------------------------------------
__device__ float g_x    [NN * DH];
__device__ float g_h    [NE * 128];
__device__ float g_ea   [NE * DH];
__device__ float g_wall [DH * WALLN];
__device__ float g_wst  [HC * DH];
__device__ float g_uall [NN * WALLN];
__device__ float g_alpha[NE * NH];       // overflow-only (deg > CAP)
__device__ float g_aggVs[NN * DH];
__device__ float g_wea  [NN * HC];
__device__ float g_aggE [NN * DH];
__device__ float g_feat [NB * FEATD];
__device__ float g_cnt  [NB];
__device__ float g_en1  [NB * 256];
__device__ float g_fc1  [NB * 1024];
__device__ int   g_deg  [NN];
__device__ int   g_off  [NN + 1];
__device__ int   g_cur  [NN];
__device__ int   g_perm [NE];

// ---------------- tf32 helpers -----------------------------------------------
__device__ __forceinline__ float f2tf32(float f)
{
    uint32_t u;
    asm("cvt.rna.tf32.f32 %0, %1;" : "=r"(u) : "f"(f));
    return __uint_as_float(u);
}

__device__ __forceinline__ void mma168(float& d0, float& d1, float& d2, float& d3,
                                       uint32_t a0, uint32_t a1, uint32_t a2, uint32_t a3,
                                       uint32_t b0, uint32_t b1)
{
    asm volatile(
        "mma.sync.aligned.m16n8k8.row.col.f32.tf32.tf32.f32 "
        "{%0,%1,%2,%3}, {%4,%5,%6,%7}, {%8,%9}, {%0,%1,%2,%3};"
        : "+f"(d0), "+f"(d1), "+f"(d2), "+f"(d3)
        : "r"(a0), "r"(a1), "r"(a2), "r"(a3), "r"(b0), "r"(b1));
}

// ---------------- tgemm: tf32 tensor-core GEMM -------------------------------
// C[M,N] = act(A[M,K] @ B[K,N] + bias). Requires K%16==0, N%4==0.
__global__ __launch_bounds__(256) void tgemm(
    const float* __restrict__ A, const float* __restrict__ B,
    const float* __restrict__ bias, float* __restrict__ C,
    int M, int K, int N, int lda, int ldb, int ldc, int flags)
{
    __shared__ float As[2][128][20];
    __shared__ float Bs[2][16][132];

    const int tid    = threadIdx.x;
    const int lane   = tid & 31;
    const int warp   = tid >> 5;
    const int warpM  = warp >> 1;
    const int warpN  = warp & 1;
    const int rowW   = warpM * 32;
    const int colW   = warpN * 64;
    const int gid    = lane >> 2;
    const int tig    = lane & 3;
    const int row0   = blockIdx.x * 128;
    const int col0   = blockIdx.y * 128;
    const int nT     = K / 16;

    float4 aReg[2], bReg[2];
    float acc[2][8][4];
#pragma unroll
    for (int mi = 0; mi < 2; mi++)
#pragma unroll
        for (int ni = 0; ni < 8; ni++)
#pragma unroll
            for (int r = 0; r < 4; r++) acc[mi][ni][r] = 0.f;

    auto fetch = [&](int kt) {
        int k0 = kt * 16;
#pragma unroll
        for (int i = 0; i < 2; i++) {
            int r = (tid >> 2) + 64 * i;
            int c = (tid & 3) * 4;
            int gr = row0 + r;
            aReg[i] = (gr < M) ? *(const float4*)(A + (size_t)gr * lda + k0 + c)
                               : make_float4(0.f, 0.f, 0.f, 0.f);
        }
#pragma unroll
        for (int i = 0; i < 2; i++) {
            int r = (tid >> 5) + 8 * i;
            int c = (tid & 31) * 4;
            int gc = col0 + c;
            bReg[i] = (gc < N) ? *(const float4*)(B + (size_t)(k0 + r) * ldb + gc)
                               : make_float4(0.f, 0.f, 0.f, 0.f);
        }
    };
    auto store = [&](int buf) {
#pragma unroll
        for (int i = 0; i < 2; i++) {
            int r = (tid >> 2) + 64 * i;
            int c = (tid & 3) * 4;
            As[buf][r][c + 0] = f2tf32(aReg[i].x);
            As[buf][r][c + 1] = f2tf32(aReg[i].y);
            As[buf][r][c + 2] = f2tf32(aReg[i].z);
            As[buf][r][c + 3] = f2tf32(aReg[i].w);
        }
#pragma unroll
        for (int i = 0; i < 2; i++) {
            int r = (tid >> 5) + 8 * i;
            int c = (tid & 31) * 4;
            Bs[buf][r][c + 0] = f2tf32(bReg[i].x);
            Bs[buf][r][c + 1] = f2tf32(bReg[i].y);
            Bs[buf][r][c + 2] = f2tf32(bReg[i].z);
            Bs[buf][r][c + 3] = f2tf32(bReg[i].w);
        }
    };

    fetch(0); store(0);
    if (nT > 1) fetch(1);
    __syncthreads();

    for (int t = 0; t < nT; t++) {
        int cur = t & 1;
#pragma unroll
        for (int k8 = 0; k8 < 16; k8 += 8) {
            uint32_t af[2][4];
#pragma unroll
            for (int mi = 0; mi < 2; mi++) {
                int r = rowW + mi * 16 + gid;
                af[mi][0] = __float_as_uint(As[cur][r    ][k8 + tig]);
                af[mi][1] = __float_as_uint(As[cur][r + 8][k8 + tig]);
                af[mi][2] = __float_as_uint(As[cur][r    ][k8 + tig + 4]);
                af[mi][3] = __float_as_uint(As[cur][r + 8][k8 + tig + 4]);
            }
            uint32_t bf[8][2];
#pragma unroll
            for (int ni = 0; ni < 8; ni++) {
                int c = colW + ni * 8 + gid;
                bf[ni][0] = __float_as_uint(Bs[cur][k8 + tig    ][c]);
                bf[ni][1] = __float_as_uint(Bs[cur][k8 + tig + 4][c]);
            }
#pragma unroll
            for (int mi = 0; mi < 2; mi++)
#pragma unroll
                for (int ni = 0; ni < 8; ni++)
                    mma168(acc[mi][ni][0], acc[mi][ni][1], acc[mi][ni][2], acc[mi][ni][3],
                           af[mi][0], af[mi][1], af[mi][2], af[mi][3],
                           bf[ni][0], bf[ni][1]);
        }
        if (t + 1 < nT) store((t + 1) & 1);
        if (t + 2 < nT) fetch(t + 2);
        __syncthreads();
    }

#pragma unroll
    for (int mi = 0; mi < 2; mi++) {
        int r0 = row0 + rowW + mi * 16 + gid;
#pragma unroll
        for (int ni = 0; ni < 8; ni++) {
            int c0 = col0 + colW + ni * 8 + tig * 2;
#pragma unroll
            for (int rr = 0; rr < 2; rr++) {
                int gr = r0 + rr * 8;
                if (gr >= M) continue;
#pragma unroll
                for (int cc = 0; cc < 2; cc++) {
                    int gc = c0 + cc;
                    if (gc >= N) continue;
                    float vv = acc[mi][ni][rr * 2 + cc];
                    if (bias) vv += bias[gc];
                    if (flags & 1) vv = vv > 0.f ? vv : 0.01f * vv;
                    C[(size_t)gr * ldc + gc] = vv;
                }
            }
        }
    }
}

// ---------------- legacy sgemm (ragged K / final layer) ----------------------
__global__ void sgemm_k(const float* __restrict__ A, const float* __restrict__ B,
                        const float* __restrict__ bias, float* __restrict__ C,
                        int M, int K, int Nn, int ldc, int act)
{
    __shared__ float As[8][128];
    __shared__ float Bs[8][128];
    const int tid = threadIdx.x;
    const int row0 = blockIdx.x * 128;
    const int col0 = blockIdx.y * 128;
    const int ty = tid >> 4;
    const int tx = tid & 15;

    float acc[8][8];
#pragma unroll
    for (int i = 0; i < 8; i++)
#pragma unroll
        for (int j = 0; j < 8; j++) acc[i][j] = 0.f;

    for (int k0 = 0; k0 < K; k0 += 8) {
#pragma unroll
        for (int i = 0; i < 4; i++) {
            int idx = tid + i * 256;
            int r = idx >> 3, c = idx & 7;
            int gr = row0 + r, gc = k0 + c;
            As[c][r] = (gr < M && gc < K) ? A[(size_t)gr * K + gc] : 0.f;
        }
#pragma unroll
        for (int i = 0; i < 4; i++) {
            int idx = tid + i * 256;
            int r = idx >> 7, c = idx & 127;
            int gr = k0 + r, gc = col0 + c;
            Bs[r][c] = (gr < K && gc < Nn) ? B[(size_t)gr * Nn + gc] : 0.f;
        }
        __syncthreads();
#pragma unroll
        for (int kk = 0; kk < 8; kk++) {
            float a[8], b[8];
#pragma unroll
            for (int i = 0; i < 8; i++) a[i] = As[kk][ty * 8 + i];
#pragma unroll
            for (int j = 0; j < 8; j++) b[j] = Bs[kk][tx * 8 + j];
#pragma unroll
            for (int i = 0; i < 8; i++)
#pragma unroll
                for (int j = 0; j < 8; j++) acc[i][j] += a[i] * b[j];
        }
        __syncthreads();
    }

#pragma unroll
    for (int i = 0; i < 8; i++) {
        int gr = row0 + ty * 8 + i;
        if (gr >= M) continue;
#pragma unroll
        for (int j = 0; j < 8; j++) {
            int gc = col0 + tx * 8 + j;
            if (gc >= Nn) continue;
            float v = acc[i][j];
            if (bias) v += bias[gc];
            if (act)  v = v > 0.f ? v : 0.01f * v;
            C[(size_t)gr * ldc + gc] = v;
        }
    }
}

// ---------------- edge MLP layer 1: h = lrelu(edge_attr[E,14] @ w1 + b1) -----
__global__ __launch_bounds__(256) void edge1_k(const float* __restrict__ ea_attr,
                                               const float* __restrict__ w1,
                                               const float* __restrict__ b1,
                                               float* __restrict__ h)
{
    __shared__ float sw1[14 * 128];
    __shared__ float sb1[128];
    int tid = threadIdx.x;
    for (int i = tid; i < 14 * 128; i += 256) sw1[i] = w1[i];
    if (tid < 128) sb1[tid] = b1[tid];
    __syncthreads();

    int e = blockIdx.x * 2 + (tid >> 7);
    int n = tid & 127;
    const float* arow = ea_attr + (size_t)e * 14;
    float acc = sb1[n];
#pragma unroll
    for (int k = 0; k < 14; k++) acc += arow[k] * sw1[k * 128 + n];
    acc = acc > 0.f ? acc : 0.01f * acc;
    h[(size_t)e * 128 + n] = acc;
}

// ---------------- weight prep: Wqk_h=Wq_h@Wk_h^T, Wqe_h=Wq_h@We_h^T ----------
__global__ __launch_bounds__(256) void wprep_k(const float* __restrict__ wq_l,
                                               const float* __restrict__ wk_l,
                                               const float* __restrict__ we_l,
                                               float* __restrict__ wall)
{
    int z = blockIdx.z;
    int h = z >> 1, which = z & 1;
    const float* A = wq_l + h * 256;
    const float* B = (which ? we_l : wk_l) + h * 256;
    float* C = wall + (which ? OFF_QW : OFF_U) + h * 256;

    __shared__ float As[16][64];
    __shared__ float Bs[16][64];
    int tid = threadIdx.x;
    int ty = tid >> 4, tx = tid & 15;
    float acc[4][4];
#pragma unroll
    for (int i = 0; i < 4; i++)
#pragma unroll
        for (int j = 0; j < 4; j++) acc[i][j] = 0.f;

    for (int k0 = 0; k0 < 256; k0 += 16) {
        int m = tid >> 2, kq = tid & 3;
        float4 a4 = *(const float4*)(A + (size_t)(blockIdx.x * 64 + m) * 1024 + k0 + kq * 4);
        As[kq * 4 + 0][m] = a4.x; As[kq * 4 + 1][m] = a4.y;
        As[kq * 4 + 2][m] = a4.z; As[kq * 4 + 3][m] = a4.w;
        float4 b4 = *(const float4*)(B + (size_t)(blockIdx.y * 64 + m) * 1024 + k0 + kq * 4);
        Bs[kq * 4 + 0][m] = b4.x; Bs[kq * 4 + 1][m] = b4.y;
        Bs[kq * 4 + 2][m] = b4.z; Bs[kq * 4 + 3][m] = b4.w;
        __syncthreads();
#pragma unroll
        for (int kk = 0; kk < 16; kk++) {
            float a[4], b[4];
#pragma unroll
            for (int i = 0; i < 4; i++) a[i] = As[kk][ty * 4 + i];
#pragma unroll
            for (int j = 0; j < 4; j++) b[j] = Bs[kk][tx * 4 + j];
#pragma unroll
            for (int i = 0; i < 4; i++)
#pragma unroll
                for (int j = 0; j < 4; j++) acc[i][j] += a[i] * b[j];
        }
        __syncthreads();
    }
#pragma unroll
    for (int i = 0; i < 4; i++)
#pragma unroll
        for (int j = 0; j < 4; j++)
            C[(size_t)(blockIdx.x * 64 + ty * 4 + i) * WALLN + blockIdx.y * 64 + tx * 4 + j] = acc[i][j];
}

// wall[:,2048:3072]=wv; wall[:,3072:3328]=wskip;  wst[h*256+d,c]=we[d,h*256+c]
__global__ void pack_k(const float* __restrict__ wv_l, const float* __restrict__ ws_l,
                       const float* __restrict__ we_l, float* __restrict__ wall,
                       float* __restrict__ wst)
{
    int i = blockIdx.x * blockDim.x + threadIdx.x;
    if (i < DH * 1280) {
        int r = i / 1280, c = i % 1280;
        wall[(size_t)r * WALLN + OFF_V + c] =
            (c < 1024) ? wv_l[r * 1024 + c] : ws_l[r * 256 + (c - 1024)];
    }
    if (i < HC * DH) {
        int r = i >> 8, c = i & 255;
        int h = r >> 8, d = r & 255;
        wst[i] = we_l[d * 1024 + h * 256 + c];
    }
}

// ---------------- CSR build --------------------------------------------------
__global__ void zero_int_k(int* p, int n)
{
    int i = blockIdx.x * blockDim.x + threadIdx.x;
    if (i < n) p[i] = 0;
}

__global__ void deg_k(const int* __restrict__ tgt, int* __restrict__ deg)
{
    int e = blockIdx.x * blockDim.x + threadIdx.x;
    if (e < NE) atomicAdd(&deg[tgt[e]], 1);
}

__global__ __launch_bounds__(1024) void scan_k(const int* __restrict__ deg,
                                               int* __restrict__ off)
{
    __shared__ int part[1024];
    int tid = threadIdx.x;
    const int per = (NN + 1023) / 1024;
    int base = tid * per;
    int s = 0;
    for (int i = 0; i < per; i++) {
        int idx = base + i;
        if (idx < NN) s += deg[idx];
    }
    part[tid] = s;
    __syncthreads();
    for (int o = 1; o < 1024; o <<= 1) {
        int v = (tid >= o) ? part[tid - o] : 0;
        __syncthreads();
        part[tid] += v;
        __syncthreads();
    }
    int run = part[tid] - s;
    for (int i = 0; i < per; i++) {
        int idx = base + i;
        if (idx < NN) { off[idx] = run; run += deg[idx]; }
    }
    if (tid == 1023) off[NN] = part[1023];
}

__global__ void fillperm_k(const int* __restrict__ tgt, int* __restrict__ cur,
                           int* __restrict__ perm)
{
    int e = blockIdx.x * blockDim.x + threadIdx.x;
    if (e >= NE) return;
    int pos = atomicAdd(&cur[tgt[e]], 1);
    perm[pos] = e;
}

// ---------------- helpers ----------------------------------------------------
__global__ void fill_k(float* p, float v, int n)
{
    int i = blockIdx.x * blockDim.x + threadIdx.x;
    if (i < n) p[i] = v;
}

__global__ void embed_k(const int* __restrict__ ids, const float* __restrict__ emb,
                        float* __restrict__ x)
{
    int i = blockIdx.x * blockDim.x + threadIdx.x;
    if (i >= NN * DH) return;
    x[i] = emb[ids[i >> 8] * DH + (i & 255)];
}

// ---------------- fused per-target edge pipeline -----------------------------
// One block per target t: logits -> softmax -> aggregation.
__global__ __launch_bounds__(256) void edge_fused_k(
    const int* __restrict__ off, const int* __restrict__ perm,
    const int* __restrict__ src, const float* __restrict__ uall,
    const float* __restrict__ x, const float* __restrict__ ea,
    float* __restrict__ galpha, float* __restrict__ aggVs, float* __restrict__ wea)
{
    __shared__ float su[1024];
    __shared__ float sqw[1024];
    __shared__ float sal[CAP * 4];
    __shared__ int   sed[CAP];
    __shared__ int   ssrc[CAP];

    const int t   = blockIdx.x;
    const int tid = threadIdx.x;
    const int b   = off[t];
    const int deg = off[t + 1] - b;

    // load u[t], qw[t] into smem (one float4 per thread each)
    const float* ub = uall + (size_t)t * WALLN;
    ((float4*)su)[tid]  = ((const float4*)(ub + OFF_U))[tid];
    ((float4*)sqw)[tid] = ((const float4*)(ub + OFF_QW))[tid];
    __syncthreads();

    // phase A: logits, warp per edge
    const int warp = tid >> 5, lane = tid & 31;
    for (int j = warp; j < deg; j += 8) {
        int e = perm[b + j];
        int s = src[e];
        if (lane == 0 && j < CAP) { sed[j] = e; ssrc[j] = s; }
        const float4* xp = (const float4*)(x + (size_t)s * 256);
        const float4* ep = (const float4*)(ea + (size_t)e * 256);
        float4 xv0 = xp[lane], xv1 = xp[lane + 32];
        float4 ev0 = ep[lane], ev1 = ep[lane + 32];
        float a[4];
#pragma unroll
        for (int h = 0; h < 4; h++) {
            const float4* up = (const float4*)(su + h * 256);
            const float4* qp = (const float4*)(sqw + h * 256);
            float4 u0 = up[lane], u1 = up[lane + 32];
            float4 q0 = qp[lane], q1 = qp[lane + 32];
            float acc = u0.x * xv0.x + u0.y * xv0.y + u0.z * xv0.z + u0.w * xv0.w
                      + u1.x * xv1.x + u1.y * xv1.y + u1.z * xv1.z + u1.w * xv1.w
                      + q0.x * ev0.x + q0.y * ev0.y + q0.z * ev0.z + q0.w * ev0.w
                      + q1.x * ev1.x + q1.y * ev1.y + q1.z * ev1.z + q1.w * ev1.w;
#pragma unroll
            for (int o = 16; o; o >>= 1) acc += __shfl_xor_sync(0xffffffffu, acc, o);
            a[h] = acc * 0.0625f;
        }
        if (lane == 0) {
            if (j < CAP) {
                sal[j * 4 + 0] = a[0]; sal[j * 4 + 1] = a[1];
                sal[j * 4 + 2] = a[2]; sal[j * 4 + 3] = a[3];
            } else {
                galpha[e * 4 + 0] = a[0]; galpha[e * 4 + 1] = a[1];
                galpha[e * 4 + 2] = a[2]; galpha[e * 4 + 3] = a[3];
            }
        }
    }
    __syncthreads();

    // phase B: softmax per head (threads 0..3)
    if (tid < 4 && deg > 0) {
        int h = tid;
        float mx = -INFINITY;
        for (int j = 0; j < deg; j++) {
            float v = (j < CAP) ? sal[j * 4 + h] : galpha[perm[b + j] * 4 + h];
            mx = fmaxf(mx, v);
        }
        float ssum = 0.f;
        for (int j = 0; j < deg; j++) {
            float v = (j < CAP) ? sal[j * 4 + h] : galpha[perm[b + j] * 4 + h];
            ssum += __expf(v - mx);
        }
        float inv = 1.f / (ssum + 1e-16f);
        for (int j = 0; j < deg; j++) {
            if (j < CAP) {
                sal[j * 4 + h] = __expf(sal[j * 4 + h] - mx) * inv;
            } else {
                int e = perm[b + j];
                galpha[e * 4 + h] = __expf(galpha[e * 4 + h] - mx) * inv;
            }
        }
    }
    __syncthreads();

    // phase C: aggregation
    const int c  = tid;
    const int idx = tid * 4;
    const int h2 = idx >> 8, d = idx & 255;
    float accV = 0.f;
    float4 accE = make_float4(0.f, 0.f, 0.f, 0.f);

    for (int j = 0; j < deg; j++) {
        int e, s;
        float a0, a1, a2, a3;
        if (j < CAP) {
            e = sed[j]; s = ssrc[j];
            a0 = sal[j * 4 + 0]; a1 = sal[j * 4 + 1];
            a2 = sal[j * 4 + 2]; a3 = sal[j * 4 + 3];
        } else {
            e = perm[b + j]; s = src[e];
            a0 = galpha[e * 4 + 0]; a1 = galpha[e * 4 + 1];
            a2 = galpha[e * 4 + 2]; a3 = galpha[e * 4 + 3];
        }
        const float* vrow = uall + (size_t)s * WALLN + OFF_V;
        accV += a0 * vrow[c] + a1 * vrow[256 + c]
              + a2 * vrow[512 + c] + a3 * vrow[768 + c];
        float ah = (h2 == 0) ? a0 : (h2 == 1) ? a1 : (h2 == 2) ? a2 : a3;
        float4 e4 = *(const float4*)(ea + (size_t)e * 256 + d);
        accE.x += ah * e4.x; accE.y += ah * e4.y;
        accE.z += ah * e4.z; accE.w += ah * e4.w;
    }
    aggVs[(size_t)t * DH + c] = accV;
    *(float4*)(wea + (size_t)t * HC + idx) = accE;
}

// x = 0.25*(aggVs + aggE) + skip  (skip lives in uall)
__global__ void combine3_k(const float* __restrict__ aggVs, const float* __restrict__ aggE,
                           const float* __restrict__ uall, float* __restrict__ x)
{
    int i = blockIdx.x * blockDim.x + threadIdx.x;
    if (i >= NN * DH) return;
    int n = i >> 8, c = i & 255;
    x[i] = 0.25f * (aggVs[i] + aggE[i]) + uall[(size_t)n * WALLN + OFF_SKIP + c];
}

__device__ __forceinline__ void atomicMaxF(float* addr, float v)
{
    if (v >= 0.f) atomicMax((int*)addr, __float_as_int(v));
    else          atomicMin((unsigned int*)addr, __float_as_uint(v));
}

__global__ void cnt_k(const int* __restrict__ batch, float* __restrict__ cnt)
{
    int n = blockIdx.x * blockDim.x + threadIdx.x;
    if (n < NN) atomicAdd(&cnt[batch[n]], 1.f);
}

__global__ void pool_init_max_k(float* __restrict__ feat)
{
    int i = blockIdx.x * blockDim.x + threadIdx.x;
    if (i >= NB * 256) return;
    feat[(i >> 8) * FEATD + 256 + (i & 255)] = __int_as_float(0xff800000u);
}

__global__ void pool_k(const int* __restrict__ batch, const float* __restrict__ x,
                       float* __restrict__ feat)
{
    int i = blockIdx.x * blockDim.x + threadIdx.x;
    if (i >= NN * DH) return;
    int n = i >> 8, c = i & 255;
    int b = batch[n];
    float v = x[i];
    atomicAdd(&feat[b * FEATD + 512 + c], v);
    atomicMaxF(&feat[b * FEATD + 256 + c], v);
}

__global__ void meanpool_k(float* __restrict__ feat, const float* __restrict__ cnt)
{
    int i = blockIdx.x * blockDim.x + threadIdx.x;
    if (i >= NB * 256) return;
    int b = i >> 8, c = i & 255;
    feat[b * FEATD + c] = feat[b * FEATD + 512 + c] / cnt[b];
}

// ---------------- launch -----------------------------------------------------
static inline dim3 g128(int M, int Nn) { return dim3((M + 127) / 128, (Nn + 127) / 128); }

extern "C" void kernel_launch(void* const* d_in, const int* in_sizes, int n_in,
                              void* d_out, int out_size)
{
    const int*   x_ids    = (const int*)  d_in[0];
    const int*   eidx     = (const int*)  d_in[1];
    const int*   batch    = (const int*)  d_in[2];
    const float* edge_attr= (const float*)d_in[3];
    const float* energies = (const float*)d_in[4];
    const float* node_emb = (const float*)d_in[5];
    const float* ew1      = (const float*)d_in[6];
    const float* eb1      = (const float*)d_in[7];
    const float* ew2      = (const float*)d_in[8];
    const float* eb2      = (const float*)d_in[9];
    const float* wq       = (const float*)d_in[10];
    const float* wk       = (const float*)d_in[11];
    const float* wv       = (const float*)d_in[12];
    const float* we       = (const float*)d_in[13];
    const float* wskip    = (const float*)d_in[14];
    const float* fce_w1   = (const float*)d_in[15];
    const float* fce_b1   = (const float*)d_in[16];
    const float* fce_w2   = (const float*)d_in[17];
    const float* fce_b2   = (const float*)d_in[18];
    const float* fc_w1    = (const float*)d_in[19];
    const float* fc_b1    = (const float*)d_in[20];
    const float* fc_w2    = (const float*)d_in[21];
    const float* fc_b2    = (const float*)d_in[22];
    float* out = (float*)d_out;

    const int* src = eidx;
    const int* tgt = eidx + NE;

    float *x, *h, *ea, *wall, *wst, *uall, *alpha, *aggVs, *wea, *aggE,
          *feat, *cnt, *en1, *fc1;
    int *deg, *off, *cur, *perm;
    cudaGetSymbolAddress((void**)&x,     g_x);
    cudaGetSymbolAddress((void**)&h,     g_h);
    cudaGetSymbolAddress((void**)&ea,    g_ea);
    cudaGetSymbolAddress((void**)&wall,  g_wall);
    cudaGetSymbolAddress((void**)&wst,   g_wst);
    cudaGetSymbolAddress((void**)&uall,  g_uall);
    cudaGetSymbolAddress((void**)&alpha, g_alpha);
    cudaGetSymbolAddress((void**)&aggVs, g_aggVs);
    cudaGetSymbolAddress((void**)&wea,   g_wea);
    cudaGetSymbolAddress((void**)&aggE,  g_aggE);
    cudaGetSymbolAddress((void**)&feat,  g_feat);
    cudaGetSymbolAddress((void**)&cnt,   g_cnt);
    cudaGetSymbolAddress((void**)&en1,   g_en1);
    cudaGetSymbolAddress((void**)&fc1,   g_fc1);
    cudaGetSymbolAddress((void**)&deg,   g_deg);
    cudaGetSymbolAddress((void**)&off,   g_off);
    cudaGetSymbolAddress((void**)&cur,   g_cur);
    cudaGetSymbolAddress((void**)&perm,  g_perm);

    // CSR build
    zero_int_k<<<(NN + 255) / 256, 256>>>(deg, NN);
    deg_k<<<(NE + 255) / 256, 256>>>(tgt, deg);
    scan_k<<<1, 1024>>>(deg, off);
    cudaMemcpyAsync(cur, off, NN * sizeof(int), cudaMemcpyDeviceToDevice);
    fillperm_k<<<(NE + 255) / 256, 256>>>(tgt, cur, perm);

    // node embedding
    embed_k<<<(NN * DH + 255) / 256, 256>>>(x_ids, node_emb, x);

    // edge MLP
    edge1_k<<<NE / 2, 256>>>(edge_attr, ew1, eb1, h);
    tgemm<<<g128(NE, 256), 256>>>(h, ew2, eb2, ea, NE, 128, 256, 128, 256, 256, 0);

    for (int l = 0; l < 3; l++) {
        const float* wql = wq + (size_t)l * DH * HC;
        const float* wkl = wk + (size_t)l * DH * HC;
        const float* wvl = wv + (size_t)l * DH * HC;
        const float* wel = we + (size_t)l * DH * HC;
        const float* wsl = wskip + (size_t)l * DH * DH;

        wprep_k<<<dim3(4, 4, 8), 256>>>(wql, wkl, wel, wall);
        pack_k<<<(DH * 1280 + 255) / 256, 256>>>(wvl, wsl, wel, wall, wst);

        // single fused node GEMM on tensor cores: uall = x @ wall
        tgemm<<<g128(NN, WALLN), 256>>>(x, wall, nullptr, uall,
                                        NN, 256, WALLN, 256, WALLN, WALLN, 0);

        // fused logits + softmax + aggregation (per target)
        edge_fused_k<<<NN, 256>>>(off, perm, src, uall, x, ea, alpha, aggVs, wea);

        // edge contribution via node GEMM on tensor cores, then combine
        tgemm<<<g128(NN, DH), 256>>>(wea, wst, nullptr, aggE,
                                     NN, 1024, 256, 1024, 256, 256, 0);
        combine3_k<<<(NN * DH + 255) / 256, 256>>>(aggVs, aggE, uall, x);
    }

    // pooling
    fill_k<<<(NB * FEATD + 255) / 256, 256>>>(feat, 0.f, NB * FEATD);
    pool_init_max_k<<<(NB * 256 + 255) / 256, 256>>>(feat);
    fill_k<<<1, NB>>>(cnt, 0.f, NB);
    cnt_k<<<(NN + 255) / 256, 256>>>(batch, cnt);
    pool_k<<<(NN * DH + 255) / 256, 256>>>(batch, x, feat);
    meanpool_k<<<(NB * 256 + 255) / 256, 256>>>(feat, cnt);

    // energies MLP (small, fp32)
    sgemm_k<<<g128(NB, 256), 256>>>(energies, fce_w1, fce_b1, en1, NB, 201, 256, 256, 1);
    sgemm_k<<<g128(NB, 128), 256>>>(en1, fce_w2, fce_b2, feat + 768, NB, 256, 128, FEATD, 0);

    // final MLP: fc1 on tensor cores, fc2 fp32 (protect output precision)
    tgemm<<<g128(NB, 1024), 256>>>(feat, fc_w1, fc_b1, fc1, NB, FEATD, 1024, FEATD, 1024, 1024, 1);
    sgemm_k<<<g128(NB, 804), 256>>>(fc1, fc_w2, fc_b2, out, NB, 1024, 804, 804, 0);
}